// round 1
// baseline (speedup 1.0000x reference)
#include <cuda_runtime.h>
#include <cuda_bf16.h>
#include <float.h>

// ---------------- problem constants (fixed by setup_inputs) ----------------
constexpr int N_ROWS  = 8 * 28 * 28;   // 6272 embedding rows
constexpr int M_BANK  = 32768;         // memory bank rows
constexpr int DIM     = 384;           // feature dim
constexpr int B_SZ    = 8;             // batch
constexpr int PATCHES = N_ROWS / B_SZ; // 784
constexpr int KNN     = 9;             // num_neighbors

constexpr int JSPLIT  = 4;             // split of M axis across blocks

// ---------------- device scratch (no allocations allowed) ----------------
__device__ float              g_xnorm[N_ROWS];
__device__ float              g_ynorm[M_BANK];
__device__ unsigned long long g_packed[N_ROWS];      // (dist2_bits << 32) | argmin
__device__ float              g_d2[B_SZ * M_BANK];
__device__ int                g_support[B_SZ * KNN];
__device__ int                g_maxrow[B_SZ];        // global embedding row of max patch
__device__ float              g_score[B_SZ];
__device__ int                g_nnidx[B_SZ];

// ---------------- helpers ----------------
__device__ __forceinline__ float warp_sum(float s) {
#pragma unroll
    for (int o = 16; o; o >>= 1) s += __shfl_xor_sync(0xFFFFFFFFu, s, o);
    return s;
}

// ---------------- k0: init packed mins ----------------
__global__ void init_packed_kernel() {
    int i = blockIdx.x * blockDim.x + threadIdx.x;
    if (i < N_ROWS) g_packed[i] = 0xFFFFFFFFFFFFFFFFull;
}

// ---------------- k1/k2: squared row norms (one warp per row) ----------------
__global__ void norms_kernel(const float* __restrict__ X, int rows, int which) {
    int warp = (blockIdx.x * blockDim.x + threadIdx.x) >> 5;
    int lane = threadIdx.x & 31;
    if (warp >= rows) return;
    const float* p = X + (size_t)warp * DIM;
    float s = 0.f;
    for (int k = lane; k < DIM; k += 32) { float v = p[k]; s += v * v; }
    s = warp_sum(s);
    if (!lane) {
        if (which == 0) g_xnorm[warp] = s;
        else            g_ynorm[warp] = s;
    }
}

// ---------------- k3: fused GEMM + min/argmin over memory bank ----------------
// 64x64 tile, 4x4 micro-tile, 256 threads, K-chunks of 16.
__global__ __launch_bounds__(256) void gemm_min_kernel(const float* __restrict__ E,
                                                       const float* __restrict__ MB) {
    __shared__ float As[16][64];
    __shared__ float Bs[16][64];
    __shared__ unsigned long long red[64][16];

    const int row0   = blockIdx.x * 64;
    const int jlen   = M_BANK / JSPLIT;
    const int j0base = blockIdx.y * jlen;
    const int t  = threadIdx.x;
    const int ty = t >> 4, tx = t & 15;     // 16x16 thread grid
    const int lr = t >> 2, lq = t & 3;      // loader mapping: 64 rows x 4 float4

    float xn[4];
#pragma unroll
    for (int i = 0; i < 4; i++) xn[i] = g_xnorm[row0 + ty * 4 + i];

    unsigned long long best[4];
#pragma unroll
    for (int i = 0; i < 4; i++) best[i] = 0xFFFFFFFFFFFFFFFFull;

    for (int j0 = j0base; j0 < j0base + jlen; j0 += 64) {
        float acc[4][4];
#pragma unroll
        for (int i = 0; i < 4; i++)
#pragma unroll
            for (int j = 0; j < 4; j++) acc[i][j] = 0.f;

        for (int k0 = 0; k0 < DIM; k0 += 16) {
            float4 av = *reinterpret_cast<const float4*>(
                &E[(size_t)(row0 + lr) * DIM + k0 + lq * 4]);
            float4 bv = *reinterpret_cast<const float4*>(
                &MB[(size_t)(j0 + lr) * DIM + k0 + lq * 4]);
            __syncthreads();
            As[lq * 4 + 0][lr] = av.x; As[lq * 4 + 1][lr] = av.y;
            As[lq * 4 + 2][lr] = av.z; As[lq * 4 + 3][lr] = av.w;
            Bs[lq * 4 + 0][lr] = bv.x; Bs[lq * 4 + 1][lr] = bv.y;
            Bs[lq * 4 + 2][lr] = bv.z; Bs[lq * 4 + 3][lr] = bv.w;
            __syncthreads();
#pragma unroll
            for (int kk = 0; kk < 16; kk++) {
                float4 a4 = *reinterpret_cast<const float4*>(&As[kk][ty * 4]);
                float4 b4 = *reinterpret_cast<const float4*>(&Bs[kk][tx * 4]);
                float ar[4] = {a4.x, a4.y, a4.z, a4.w};
                float br[4] = {b4.x, b4.y, b4.z, b4.w};
#pragma unroll
                for (int i = 0; i < 4; i++)
#pragma unroll
                    for (int j = 0; j < 4; j++)
                        acc[i][j] = fmaf(ar[i], br[j], acc[i][j]);
            }
        }
        // fold this 64-col tile into running mins
#pragma unroll
        for (int j = 0; j < 4; j++) {
            int jg = j0 + tx * 4 + j;
            float yn = g_ynorm[jg];
#pragma unroll
            for (int i = 0; i < 4; i++) {
                float d = fmaxf(xn[i] + yn - 2.f * acc[i][j], 0.f);
                unsigned long long p =
                    ((unsigned long long)__float_as_uint(d) << 32) | (unsigned)jg;
                best[i] = (p < best[i]) ? p : best[i];
            }
        }
    }

    __syncthreads();
#pragma unroll
    for (int i = 0; i < 4; i++) red[ty * 4 + i][tx] = best[i];
    __syncthreads();
    if (t < 64) {
        unsigned long long m = 0xFFFFFFFFFFFFFFFFull;
#pragma unroll
        for (int q = 0; q < 16; q++) {
            unsigned long long v = red[t][q];
            m = (v < m) ? v : m;
        }
        atomicMin(&g_packed[row0 + t], m);
    }
}

// ---------------- k4: per-batch argmax patch, extract score/nn ----------------
__global__ void batch_reduce_kernel() {
    int b = blockIdx.x;
    int t = threadIdx.x;  // 256
    __shared__ float sv[256];
    __shared__ int   si[256];
    float bv = -1.f;
    int   bi = PATCHES;  // larger than any real index
    for (int p = t; p < PATCHES; p += 256) {
        unsigned long long pk = g_packed[b * PATCHES + p];
        float d = __uint_as_float((unsigned)(pk >> 32));
        if (d > bv || (d == bv && p < bi)) { bv = d; bi = p; }
    }
    sv[t] = bv; si[t] = bi;
    __syncthreads();
    for (int s = 128; s; s >>= 1) {
        if (t < s) {
            if (sv[t + s] > sv[t] || (sv[t + s] == sv[t] && si[t + s] < si[t])) {
                sv[t] = sv[t + s]; si[t] = si[t + s];
            }
        }
        __syncthreads();
    }
    if (t == 0) {
        int row = b * PATCHES + si[0];
        unsigned long long pk = g_packed[row];
        g_maxrow[b] = row;
        g_score[b]  = sqrtf(__uint_as_float((unsigned)(pk >> 32)));
        g_nnidx[b]  = (int)(pk & 0xFFFFFFFFull);
    }
}

// ---------------- k5: write patch map ----------------
__global__ void write_map_kernel(float* __restrict__ out) {
    int i = blockIdx.x * blockDim.x + threadIdx.x;
    if (i < N_ROWS)
        out[i] = sqrtf(__uint_as_float((unsigned)(g_packed[i] >> 32)));
}

// ---------------- k6: d2 = dist^2(nn_sample[b], memory_bank) ----------------
__global__ void d2_kernel(const float* __restrict__ MB) {
    int b    = blockIdx.y;
    int wid  = threadIdx.x >> 5;
    int lane = threadIdx.x & 31;
    int m    = blockIdx.x * 8 + wid;
    int nn   = g_nnidx[b];
    const float* pn = MB + (size_t)nn * DIM;
    const float* pm = MB + (size_t)m * DIM;
    float s = 0.f;
    for (int k = lane; k < DIM; k += 32) s += pn[k] * pm[k];
    s = warp_sum(s);
    if (!lane)
        g_d2[b * M_BANK + m] = fmaxf(g_ynorm[nn] + g_ynorm[m] - 2.f * s, 0.f);
}

// ---------------- k7: top-9 smallest d2 per batch (sequential selection) ------
__global__ void topk_kernel() {
    int b = blockIdx.x;
    int t = threadIdx.x;  // 256
    __shared__ float sv[256];
    __shared__ int   si[256];
    __shared__ int   sel[KNN];
    for (int r = 0; r < KNN; r++) {
        float bv = FLT_MAX;
        int   bi = M_BANK;
        for (int m = t; m < M_BANK; m += 256) {
            float v = g_d2[b * M_BANK + m];
            bool excl = false;
            for (int q = 0; q < r; q++) if (sel[q] == m) excl = true;
            if (!excl && (v < bv || (v == bv && m < bi))) { bv = v; bi = m; }
        }
        sv[t] = bv; si[t] = bi;
        __syncthreads();
        for (int s = 128; s; s >>= 1) {
            if (t < s) {
                if (sv[t + s] < sv[t] || (sv[t + s] == sv[t] && si[t + s] < si[t])) {
                    sv[t] = sv[t + s]; si[t] = si[t + s];
                }
            }
            __syncthreads();
        }
        if (t == 0) { sel[r] = si[0]; g_support[b * KNN + r] = si[0]; }
        __syncthreads();
    }
}

// ---------------- k8: d3, softmax weight, pred_score ----------------
__global__ void final_kernel(const float* __restrict__ E,
                             const float* __restrict__ MB,
                             float* __restrict__ out) {
    int b    = blockIdx.x;
    int wid  = threadIdx.x >> 5;   // 9 warps, one per neighbor
    int lane = threadIdx.x & 31;
    __shared__ float d3[KNN];
    int row = g_maxrow[b];
    const float* xf = E + (size_t)row * DIM;
    int sup = g_support[b * KNN + wid];
    const float* pv = MB + (size_t)sup * DIM;
    float s = 0.f;
    for (int k = lane; k < DIM; k += 32) s += xf[k] * pv[k];
    s = warp_sum(s);
    if (!lane)
        d3[wid] = sqrtf(fmaxf(g_xnorm[row] + g_ynorm[sup] - 2.f * s, 0.f));
    __syncthreads();
    if (threadIdx.x == 0) {
        float mx = -FLT_MAX;
        for (int j = 0; j < KNN; j++) mx = fmaxf(mx, d3[j]);
        float den = 0.f, e0 = 0.f;
        for (int j = 0; j < KNN; j++) {
            float e = expf(d3[j] - mx);
            den += e;
            if (j == 0) e0 = e;
        }
        float w = 1.f - e0 / den;
        out[N_ROWS + b] = w * g_score[b];
    }
}

// ---------------- launch ----------------
extern "C" void kernel_launch(void* const* d_in, const int* in_sizes, int n_in,
                              void* d_out, int out_size) {
    (void)n_in; (void)in_sizes; (void)out_size;
    const float* E  = (const float*)d_in[0];   // [6272, 384]
    const float* MB = (const float*)d_in[1];   // [32768, 384]
    float* out = (float*)d_out;                // [6272 patch_map | 8 pred_score]

    init_packed_kernel<<<(N_ROWS + 255) / 256, 256>>>();
    norms_kernel<<<(N_ROWS * 32 + 255) / 256, 256>>>(E, N_ROWS, 0);
    norms_kernel<<<(M_BANK * 32 + 255) / 256, 256>>>(MB, M_BANK, 1);

    dim3 grid(N_ROWS / 64, JSPLIT);
    gemm_min_kernel<<<grid, 256>>>(E, MB);

    batch_reduce_kernel<<<B_SZ, 256>>>();
    write_map_kernel<<<(N_ROWS + 255) / 256, 256>>>(out);
    d2_kernel<<<dim3(M_BANK / 8, B_SZ), 256>>>(MB);
    topk_kernel<<<B_SZ, 256>>>();
    final_kernel<<<B_SZ, KNN * 32>>>(E, MB, out);
}

// round 3
// speedup vs baseline: 3.9909x; 3.9909x over previous
#include <cuda_runtime.h>
#include <cuda_bf16.h>
#include <float.h>
#include <stdint.h>

// ---------------- problem constants ----------------
constexpr int N_ROWS  = 6272;
constexpr int M_BANK  = 32768;
constexpr int DIM     = 384;
constexpr int B_SZ    = 8;
constexpr int PATCHES = N_ROWS / B_SZ;
constexpr int KNN     = 9;

// ---------------- GEMM tiling ----------------
constexpr int BM = 128;
constexpr int BN = 256;
constexpr int BK = 64;                 // halves per chunk = 128 bytes/row
constexpr int NSTAGE_K = DIM / BK;     // 6
constexpr int GRID_Y   = 8;
constexpr int JT_PER_CTA = (M_BANK / BN) / GRID_Y;  // 16
constexpr int ROW_TILES  = N_ROWS / BM;             // 49

// SMEM stage layout (bytes)
constexpr int OFF_AH = 0;
constexpr int OFF_AL = BM * 128;             // 16384
constexpr int OFF_BH = 2 * BM * 128;         // 32768
constexpr int OFF_BL = 2 * BM * 128 + BN * 128;   // 65536
constexpr int STAGE_BYTES = 2 * BM * 128 + 2 * BN * 128;  // 98304
constexpr int RED_OFF     = 2 * STAGE_BYTES;               // 196608
constexpr int SMEM_BYTES  = RED_OFF + BM * 8;              // +1KB reduce

// ---------------- device scratch ----------------
__device__ __align__(256) __nv_bfloat16 g_Eh[N_ROWS * DIM];
__device__ __align__(256) __nv_bfloat16 g_El[N_ROWS * DIM];
__device__ __align__(256) __nv_bfloat16 g_Bh[M_BANK * DIM];
__device__ __align__(256) __nv_bfloat16 g_Bl[M_BANK * DIM];
__device__ float              g_xnorm[N_ROWS];
__device__ float              g_ynorm[M_BANK];
__device__ unsigned long long g_packed[N_ROWS];
__device__ float              g_d2[B_SZ * M_BANK];
__device__ int                g_support[B_SZ * KNN];
__device__ int                g_maxrow[B_SZ];
__device__ float              g_score[B_SZ];
__device__ int                g_nnidx[B_SZ];

// ---------------- helpers ----------------
__device__ __forceinline__ uint32_t smem_u32(const void* p) {
    uint32_t a;
    asm("{ .reg .u64 t; cvta.to.shared.u64 t, %1; cvt.u32.u64 %0, t; }"
        : "=r"(a) : "l"(p));
    return a;
}
__device__ __forceinline__ void cp16(uint32_t dst, const void* src) {
    asm volatile("cp.async.cg.shared.global [%0], [%1], 16;"
                 :: "r"(dst), "l"(src) : "memory");
}
#define CP_COMMIT() asm volatile("cp.async.commit_group;" ::: "memory")
#define CP_WAIT1()  asm volatile("cp.async.wait_group 1;" ::: "memory")
#define CP_WAIT0()  asm volatile("cp.async.wait_group 0;" ::: "memory")

__device__ __forceinline__ uint32_t swz(uint32_t o) { return o ^ ((o >> 3) & 0x70); }

__device__ __forceinline__ void ldmA(uint32_t base, int r_base, int kb,
                                     int lane, uint32_t* f) {
    int q = lane >> 3;
    int r = r_base + (q & 1) * 8 + (lane & 7);
    int kk = kb + (q >> 1) * 16;
    uint32_t a = base + swz((uint32_t)(r * 128 + kk));
    asm volatile("ldmatrix.sync.aligned.m8n8.x4.shared.b16 {%0,%1,%2,%3}, [%4];"
                 : "=r"(f[0]), "=r"(f[1]), "=r"(f[2]), "=r"(f[3]) : "r"(a));
}
// loads two adjacent n-atoms (16 cols) worth of B fragments
__device__ __forceinline__ void ldmB4(uint32_t base, int n_base, int kb,
                                      int lane, uint32_t* f) {
    int q = lane >> 3;
    int n = n_base + (q >> 1) * 8 + (lane & 7);
    int kk = kb + (q & 1) * 16;
    uint32_t a = base + swz((uint32_t)(n * 128 + kk));
    asm volatile("ldmatrix.sync.aligned.m8n8.x4.shared.b16 {%0,%1,%2,%3}, [%4];"
                 : "=r"(f[0]), "=r"(f[1]), "=r"(f[2]), "=r"(f[3]) : "r"(a));
}
__device__ __forceinline__ void mma_bf16(float* c, const uint32_t* a,
                                         const uint32_t* b) {
    asm volatile(
        "mma.sync.aligned.m16n8k16.row.col.f32.bf16.bf16.f32 "
        "{%0,%1,%2,%3},{%4,%5,%6,%7},{%8,%9},{%0,%1,%2,%3};"
        : "+f"(c[0]), "+f"(c[1]), "+f"(c[2]), "+f"(c[3])
        : "r"(a[0]), "r"(a[1]), "r"(a[2]), "r"(a[3]), "r"(b[0]), "r"(b[1]));
}
__device__ __forceinline__ float warp_sum(float s) {
#pragma unroll
    for (int o = 16; o; o >>= 1) s += __shfl_xor_sync(0xFFFFFFFFu, s, o);
    return s;
}
__device__ __forceinline__ void fold_min(unsigned long long& best, float xn,
                                         float yn, float dot, int col) {
    float d = fmaxf(fmaf(-2.f, dot, xn + yn), 0.f);
    unsigned long long p =
        ((unsigned long long)__float_as_uint(d) << 32) | (unsigned)col;
    best = (p < best) ? p : best;
}

// ---------------- prep kernels ----------------
__global__ void split_kernel(const float* __restrict__ X, int which) {
    int i = blockIdx.x * blockDim.x + threadIdx.x;
    int n = which ? M_BANK * DIM : N_ROWS * DIM;
    if (i >= n) return;
    float x = X[i];
    __nv_bfloat16 h = __float2bfloat16(x);
    __nv_bfloat16 l = __float2bfloat16(x - __bfloat162float(h));
    if (which) { g_Bh[i] = h; g_Bl[i] = l; }
    else       { g_Eh[i] = h; g_El[i] = l; }
}

__global__ void init_packed_kernel() {
    int i = blockIdx.x * blockDim.x + threadIdx.x;
    if (i < N_ROWS) g_packed[i] = 0xFFFFFFFFFFFFFFFFull;
}

__global__ void norms_kernel(const float* __restrict__ X, int rows, int which) {
    int warp = (blockIdx.x * blockDim.x + threadIdx.x) >> 5;
    int lane = threadIdx.x & 31;
    if (warp >= rows) return;
    const float* p = X + (size_t)warp * DIM;
    float s = 0.f;
    for (int k = lane; k < DIM; k += 32) { float v = p[k]; s += v * v; }
    s = warp_sum(s);
    if (!lane) { if (which == 0) g_xnorm[warp] = s; else g_ynorm[warp] = s; }
}

// ---------------- stage loader ----------------
__device__ __forceinline__ void load_stage(uint32_t sb, int buf, int row0,
                                           int j0, int ck, int t) {
    uint32_t sbase = sb + buf * STAGE_BYTES;
    int kofs = ck * BK;
#pragma unroll 4
    for (int i = t; i < BM * 8; i += 256) {
        int r = i >> 3, g = i & 7;
        uint32_t d = swz((uint32_t)(r * 128 + g * 16));
        size_t gof = (size_t)(row0 + r) * DIM + kofs + g * 8;
        cp16(sbase + OFF_AH + d, g_Eh + gof);
        cp16(sbase + OFF_AL + d, g_El + gof);
    }
#pragma unroll 8
    for (int i = t; i < BN * 8; i += 256) {
        int r = i >> 3, g = i & 7;
        uint32_t d = swz((uint32_t)(r * 128 + g * 16));
        size_t gof = (size_t)(j0 + r) * DIM + kofs + g * 8;
        cp16(sbase + OFF_BH + d, g_Bh + gof);
        cp16(sbase + OFF_BL + d, g_Bl + gof);
    }
}

// ---------------- main GEMM + fused min/argmin ----------------
__global__ __launch_bounds__(256, 1) void gemm_mma_kernel() {
    extern __shared__ __align__(1024) char smem[];
    uint32_t sb = smem_u32(smem);
    unsigned long long* red = (unsigned long long*)(smem + RED_OFF);

    const int t = threadIdx.x;
    const int w = t >> 5, lane = t & 31;
    const int gid = lane >> 2, tig = lane & 3;
    const int wm = w & 1, wn = w >> 1;     // warp tile: rows wm*64, cols wn*64
    const int row0 = blockIdx.x * BM;

    float xnA[4], xnB[4];
#pragma unroll
    for (int i = 0; i < 4; i++) {
        xnA[i] = g_xnorm[row0 + wm * 64 + i * 16 + gid];
        xnB[i] = g_xnorm[row0 + wm * 64 + i * 16 + gid + 8];
    }

    unsigned long long bestA[4], bestB[4];
#pragma unroll
    for (int i = 0; i < 4; i++) bestA[i] = bestB[i] = 0xFFFFFFFFFFFFFFFFull;

    for (int jt = 0; jt < JT_PER_CTA; jt++) {
        const int j0 = (blockIdx.y * JT_PER_CTA + jt) * BN;

        float acc[4][8][4];
#pragma unroll
        for (int i = 0; i < 4; i++)
#pragma unroll
            for (int j = 0; j < 8; j++)
#pragma unroll
                for (int q = 0; q < 4; q++) acc[i][j][q] = 0.f;

        load_stage(sb, 0, row0, j0, 0, t);
        CP_COMMIT();

        for (int s = 0; s < NSTAGE_K; s++) {
            if (s + 1 < NSTAGE_K) {
                load_stage(sb, (s + 1) & 1, row0, j0, s + 1, t);
                CP_COMMIT();
                CP_WAIT1();
            } else {
                CP_WAIT0();
            }
            __syncthreads();
            const uint32_t st = sb + (s & 1) * STAGE_BYTES;
            const uint32_t sAh = st + OFF_AH, sAl = st + OFF_AL;
            const uint32_t sBh = st + OFF_BH, sBl = st + OFF_BL;

#pragma unroll
            for (int kk = 0; kk < BK / 16; kk++) {
                const int kb = kk * 32;   // bytes
                uint32_t Ah[4][4], Al[4][4], Bf[8][2];
#pragma unroll
                for (int i = 0; i < 4; i++)
                    ldmA(sAh, wm * 64 + i * 16, kb, lane, Ah[i]);
#pragma unroll
                for (int jj = 0; jj < 4; jj++) {
                    uint32_t f[4];
                    ldmB4(sBh, wn * 64 + jj * 16, kb, lane, f);
                    Bf[2 * jj][0] = f[0]; Bf[2 * jj][1] = f[1];
                    Bf[2 * jj + 1][0] = f[2]; Bf[2 * jj + 1][1] = f[3];
                }
#pragma unroll
                for (int i = 0; i < 4; i++)
#pragma unroll
                    for (int j = 0; j < 8; j++)
                        mma_bf16(acc[i][j], Ah[i], Bf[j]);   // hi*hi
#pragma unroll
                for (int i = 0; i < 4; i++)
                    ldmA(sAl, wm * 64 + i * 16, kb, lane, Al[i]);
#pragma unroll
                for (int i = 0; i < 4; i++)
#pragma unroll
                    for (int j = 0; j < 8; j++)
                        mma_bf16(acc[i][j], Al[i], Bf[j]);   // lo*hi
#pragma unroll
                for (int jj = 0; jj < 4; jj++) {
                    uint32_t f[4];
                    ldmB4(sBl, wn * 64 + jj * 16, kb, lane, f);
                    Bf[2 * jj][0] = f[0]; Bf[2 * jj][1] = f[1];
                    Bf[2 * jj + 1][0] = f[2]; Bf[2 * jj + 1][1] = f[3];
                }
#pragma unroll
                for (int i = 0; i < 4; i++)
#pragma unroll
                    for (int j = 0; j < 8; j++)
                        mma_bf16(acc[i][j], Ah[i], Bf[j]);   // hi*lo
            }
            __syncthreads();
        }

        // fold this j-tile into running per-thread mins
        float yn0[8], yn1[8];
#pragma unroll
        for (int j = 0; j < 8; j++) {
            int c = j0 + wn * 64 + j * 8 + tig * 2;
            yn0[j] = g_ynorm[c];
            yn1[j] = g_ynorm[c + 1];
        }
#pragma unroll
        for (int i = 0; i < 4; i++)
#pragma unroll
            for (int j = 0; j < 8; j++) {
                int c = j0 + wn * 64 + j * 8 + tig * 2;
                fold_min(bestA[i], xnA[i], yn0[j], acc[i][j][0], c);
                fold_min(bestA[i], xnA[i], yn1[j], acc[i][j][1], c + 1);
                fold_min(bestB[i], xnB[i], yn0[j], acc[i][j][2], c);
                fold_min(bestB[i], xnB[i], yn1[j], acc[i][j][3], c + 1);
            }
    }

    // reduce across tig lanes (same row, different cols)
#pragma unroll
    for (int i = 0; i < 4; i++) {
#pragma unroll
        for (int off = 1; off <= 2; off <<= 1) {
            unsigned long long va =
                __shfl_xor_sync(0xFFFFFFFFu, bestA[i], off);
            unsigned long long vb =
                __shfl_xor_sync(0xFFFFFFFFu, bestB[i], off);
            bestA[i] = (va < bestA[i]) ? va : bestA[i];
            bestB[i] = (vb < bestB[i]) ? vb : bestB[i];
        }
    }

    if (t < BM) red[t] = 0xFFFFFFFFFFFFFFFFull;
    __syncthreads();
    if (tig == 0) {
#pragma unroll
        for (int i = 0; i < 4; i++) {
            atomicMin(&red[wm * 64 + i * 16 + gid], bestA[i]);
            atomicMin(&red[wm * 64 + i * 16 + gid + 8], bestB[i]);
        }
    }
    __syncthreads();
    if (t < BM) atomicMin(&g_packed[row0 + t], red[t]);
}

// ---------------- tail kernels ----------------
__global__ void batch_reduce_kernel() {
    int b = blockIdx.x, t = threadIdx.x;
    __shared__ float sv[256];
    __shared__ int   si[256];
    float bv = -1.f; int bi = PATCHES;
    for (int p = t; p < PATCHES; p += 256) {
        unsigned long long pk = g_packed[b * PATCHES + p];
        float d = __uint_as_float((unsigned)(pk >> 32));
        if (d > bv || (d == bv && p < bi)) { bv = d; bi = p; }
    }
    sv[t] = bv; si[t] = bi;
    __syncthreads();
    for (int s = 128; s; s >>= 1) {
        if (t < s) {
            if (sv[t + s] > sv[t] || (sv[t + s] == sv[t] && si[t + s] < si[t])) {
                sv[t] = sv[t + s]; si[t] = si[t + s];
            }
        }
        __syncthreads();
    }
    if (t == 0) {
        int row = b * PATCHES + si[0];
        unsigned long long pk = g_packed[row];
        g_maxrow[b] = row;
        g_score[b]  = sqrtf(__uint_as_float((unsigned)(pk >> 32)));
        g_nnidx[b]  = (int)(pk & 0xFFFFFFFFull);
    }
}

__global__ void write_map_kernel(float* __restrict__ out) {
    int i = blockIdx.x * blockDim.x + threadIdx.x;
    if (i < N_ROWS)
        out[i] = sqrtf(__uint_as_float((unsigned)(g_packed[i] >> 32)));
}

__global__ void d2_kernel(const float* __restrict__ MB) {
    int b = blockIdx.y;
    int wid = threadIdx.x >> 5, lane = threadIdx.x & 31;
    int m = blockIdx.x * 8 + wid;
    int nn = g_nnidx[b];
    const float* pn = MB + (size_t)nn * DIM;
    const float* pm = MB + (size_t)m * DIM;
    float s = 0.f;
    for (int k = lane; k < DIM; k += 32) s += pn[k] * pm[k];
    s = warp_sum(s);
    if (!lane)
        g_d2[b * M_BANK + m] = fmaxf(g_ynorm[nn] + g_ynorm[m] - 2.f * s, 0.f);
}

__global__ void topk_kernel() {
    int b = blockIdx.x, t = threadIdx.x;
    __shared__ float sv[256];
    __shared__ int   si[256];
    __shared__ int   sel[KNN];
    for (int r = 0; r < KNN; r++) {
        float bv = FLT_MAX; int bi = M_BANK;
        for (int m = t; m < M_BANK; m += 256) {
            float v = g_d2[b * M_BANK + m];
            bool excl = false;
            for (int q = 0; q < r; q++) if (sel[q] == m) excl = true;
            if (!excl && (v < bv || (v == bv && m < bi))) { bv = v; bi = m; }
        }
        sv[t] = bv; si[t] = bi;
        __syncthreads();
        for (int s = 128; s; s >>= 1) {
            if (t < s) {
                if (sv[t + s] < sv[t] || (sv[t + s] == sv[t] && si[t + s] < si[t])) {
                    sv[t] = sv[t + s]; si[t] = si[t + s];
                }
            }
            __syncthreads();
        }
        if (t == 0) { sel[r] = si[0]; g_support[b * KNN + r] = si[0]; }
        __syncthreads();
    }
}

__global__ void final_kernel(const float* __restrict__ E,
                             const float* __restrict__ MB,
                             float* __restrict__ out) {
    int b = blockIdx.x;
    int wid = threadIdx.x >> 5, lane = threadIdx.x & 31;
    __shared__ float d3[KNN];
    int row = g_maxrow[b];
    const float* xf = E + (size_t)row * DIM;
    int sup = g_support[b * KNN + wid];
    const float* pv = MB + (size_t)sup * DIM;
    float s = 0.f;
    for (int k = lane; k < DIM; k += 32) s += xf[k] * pv[k];
    s = warp_sum(s);
    if (!lane)
        d3[wid] = sqrtf(fmaxf(g_xnorm[row] + g_ynorm[sup] - 2.f * s, 0.f));
    __syncthreads();
    if (threadIdx.x == 0) {
        float mx = -FLT_MAX;
        for (int j = 0; j < KNN; j++) mx = fmaxf(mx, d3[j]);
        float den = 0.f, e0 = 0.f;
        for (int j = 0; j < KNN; j++) {
            float e = expf(d3[j] - mx);
            den += e;
            if (j == 0) e0 = e;
        }
        out[N_ROWS + b] = (1.f - e0 / den) * g_score[b];
    }
}

// ---------------- launch ----------------
extern "C" void kernel_launch(void* const* d_in, const int* in_sizes, int n_in,
                              void* d_out, int out_size) {
    (void)n_in; (void)in_sizes; (void)out_size;
    const float* E  = (const float*)d_in[0];
    const float* MB = (const float*)d_in[1];
    float* out = (float*)d_out;

    cudaFuncSetAttribute(gemm_mma_kernel,
                         cudaFuncAttributeMaxDynamicSharedMemorySize, SMEM_BYTES);

    split_kernel<<<(N_ROWS * DIM + 255) / 256, 256>>>(E, 0);
    split_kernel<<<(M_BANK * DIM + 255) / 256, 256>>>(MB, 1);
    init_packed_kernel<<<(N_ROWS + 255) / 256, 256>>>();
    norms_kernel<<<(N_ROWS * 32 + 255) / 256, 256>>>(E, N_ROWS, 0);
    norms_kernel<<<(M_BANK * 32 + 255) / 256, 256>>>(MB, M_BANK, 1);

    gemm_mma_kernel<<<dim3(ROW_TILES, GRID_Y), 256, SMEM_BYTES>>>();

    batch_reduce_kernel<<<B_SZ, 256>>>();
    write_map_kernel<<<(N_ROWS + 255) / 256, 256>>>(out);
    d2_kernel<<<dim3(M_BANK / 8, B_SZ), 256>>>(MB);
    topk_kernel<<<B_SZ, 256>>>();
    final_kernel<<<B_SZ, KNN * 32>>>(E, MB, out);
}

// round 4
// speedup vs baseline: 5.7535x; 1.4416x over previous
#include <cuda_runtime.h>
#include <cuda_fp16.h>
#include <float.h>
#include <stdint.h>

// ---------------- problem constants ----------------
constexpr int N_ROWS  = 6272;
constexpr int M_BANK  = 32768;
constexpr int DIM     = 384;
constexpr int B_SZ    = 8;
constexpr int PATCHES = N_ROWS / B_SZ;
constexpr int KNN     = 9;

// ---------------- GEMM tiling ----------------
constexpr int BM = 128;
constexpr int BN = 256;
constexpr int BK = 64;                 // halves per chunk = 128 bytes/row
constexpr int NSTAGE_K = DIM / BK;     // 6
constexpr int JT_TOTAL = M_BANK / BN;  // 128
constexpr int GRID_Y   = 3;            // 43+43+42 j-tiles -> 147 CTAs = 1 wave
constexpr int ROW_TILES = N_ROWS / BM; // 49

// SMEM stage layout (bytes)
constexpr int OFF_AH = 0;
constexpr int OFF_AL = BM * 128;            // 16384
constexpr int OFF_B  = 2 * BM * 128;        // 32768
constexpr int STAGE_BYTES = 2 * BM * 128 + BN * 128;   // 65536
constexpr int RED_OFF     = 2 * STAGE_BYTES;            // 131072
constexpr int SMEM_BYTES  = RED_OFF + BM * 8;

// ---------------- device scratch ----------------
__device__ __align__(256) __half g_Eh[N_ROWS * DIM];
__device__ __align__(256) __half g_El[N_ROWS * DIM];
__device__ __align__(256) __half g_Bh[M_BANK * DIM];
__device__ float              g_xnorm[N_ROWS];
__device__ float              g_ynorm[M_BANK];
__device__ unsigned long long g_packed[N_ROWS];
__device__ float              g_d2[B_SZ * M_BANK];
__device__ int                g_support[B_SZ * KNN];
__device__ int                g_maxrow[B_SZ];
__device__ float              g_score[B_SZ];
__device__ int                g_nnidx[B_SZ];

// ---------------- helpers ----------------
__device__ __forceinline__ uint32_t smem_u32(const void* p) {
    uint32_t a;
    asm("{ .reg .u64 t; cvta.to.shared.u64 t, %1; cvt.u32.u64 %0, t; }"
        : "=r"(a) : "l"(p));
    return a;
}
__device__ __forceinline__ void cp16(uint32_t dst, const void* src) {
    asm volatile("cp.async.cg.shared.global [%0], [%1], 16;"
                 :: "r"(dst), "l"(src) : "memory");
}
#define CP_COMMIT() asm volatile("cp.async.commit_group;" ::: "memory")
#define CP_WAIT1()  asm volatile("cp.async.wait_group 1;" ::: "memory")
#define CP_WAIT0()  asm volatile("cp.async.wait_group 0;" ::: "memory")

__device__ __forceinline__ uint32_t swz(uint32_t o) { return o ^ ((o >> 3) & 0x70); }

__device__ __forceinline__ void ldmA(uint32_t base, int r_base, int kb,
                                     int lane, uint32_t* f) {
    int q = lane >> 3;
    int r = r_base + (q & 1) * 8 + (lane & 7);
    int kk = kb + (q >> 1) * 16;
    uint32_t a = base + swz((uint32_t)(r * 128 + kk));
    asm volatile("ldmatrix.sync.aligned.m8n8.x4.shared.b16 {%0,%1,%2,%3}, [%4];"
                 : "=r"(f[0]), "=r"(f[1]), "=r"(f[2]), "=r"(f[3]) : "r"(a));
}
__device__ __forceinline__ void ldmB4(uint32_t base, int n_base, int kb,
                                      int lane, uint32_t* f) {
    int q = lane >> 3;
    int n = n_base + (q >> 1) * 8 + (lane & 7);
    int kk = kb + (q & 1) * 16;
    uint32_t a = base + swz((uint32_t)(n * 128 + kk));
    asm volatile("ldmatrix.sync.aligned.m8n8.x4.shared.b16 {%0,%1,%2,%3}, [%4];"
                 : "=r"(f[0]), "=r"(f[1]), "=r"(f[2]), "=r"(f[3]) : "r"(a));
}
__device__ __forceinline__ void mma_f16(float* c, const uint32_t* a,
                                        const uint32_t* b) {
    asm volatile(
        "mma.sync.aligned.m16n8k16.row.col.f32.f16.f16.f32 "
        "{%0,%1,%2,%3},{%4,%5,%6,%7},{%8,%9},{%0,%1,%2,%3};"
        : "+f"(c[0]), "+f"(c[1]), "+f"(c[2]), "+f"(c[3])
        : "r"(a[0]), "r"(a[1]), "r"(a[2]), "r"(a[3]), "r"(b[0]), "r"(b[1]));
}
__device__ __forceinline__ float warp_sum(float s) {
#pragma unroll
    for (int o = 16; o; o >>= 1) s += __shfl_xor_sync(0xFFFFFFFFu, s, o);
    return s;
}
__device__ __forceinline__ void fold_min(unsigned long long& best, float xn,
                                         float yn, float dot, int col) {
    float d = fmaxf(fmaf(-2.f, dot, xn + yn), 0.f);
    unsigned long long p =
        ((unsigned long long)__float_as_uint(d) << 32) | (unsigned)col;
    best = (p < best) ? p : best;
}

// ---------------- prep kernels ----------------
__global__ void split_kernel(const float* __restrict__ X, int which) {
    int i = blockIdx.x * blockDim.x + threadIdx.x;
    int n = which ? M_BANK * DIM : N_ROWS * DIM;
    if (i >= n) return;
    float x = X[i];
    __half h = __float2half_rn(x);
    if (which) {
        g_Bh[i] = h;
    } else {
        g_Eh[i] = h;
        g_El[i] = __float2half_rn(x - __half2float(h));
    }
}

__global__ void init_packed_kernel() {
    int i = blockIdx.x * blockDim.x + threadIdx.x;
    if (i < N_ROWS) g_packed[i] = 0xFFFFFFFFFFFFFFFFull;
}

__global__ void norms_kernel(const float* __restrict__ X, int rows, int which) {
    int warp = (blockIdx.x * blockDim.x + threadIdx.x) >> 5;
    int lane = threadIdx.x & 31;
    if (warp >= rows) return;
    const float* p = X + (size_t)warp * DIM;
    float s = 0.f;
    for (int k = lane; k < DIM; k += 32) { float v = p[k]; s += v * v; }
    s = warp_sum(s);
    if (!lane) { if (which == 0) g_xnorm[warp] = s; else g_ynorm[warp] = s; }
}

// ---------------- stage loader ----------------
__device__ __forceinline__ void load_stage(uint32_t sb, int buf, int row0,
                                           int j0, int ck, int t) {
    uint32_t sbase = sb + buf * STAGE_BYTES;
    int kofs = ck * BK;
#pragma unroll 4
    for (int i = t; i < BM * 8; i += 256) {
        int r = i >> 3, g = i & 7;
        uint32_t d = swz((uint32_t)(r * 128 + g * 16));
        size_t gof = (size_t)(row0 + r) * DIM + kofs + g * 8;
        cp16(sbase + OFF_AH + d, g_Eh + gof);
        cp16(sbase + OFF_AL + d, g_El + gof);
    }
#pragma unroll 8
    for (int i = t; i < BN * 8; i += 256) {
        int r = i >> 3, g = i & 7;
        uint32_t d = swz((uint32_t)(r * 128 + g * 16));
        size_t gof = (size_t)(j0 + r) * DIM + kofs + g * 8;
        cp16(sbase + OFF_B + d, g_Bh + gof);
    }
}

// ---------------- main GEMM + fused min/argmin ----------------
__global__ __launch_bounds__(256, 1) void gemm_mma_kernel() {
    extern __shared__ __align__(1024) char smem[];
    uint32_t sb = smem_u32(smem);
    unsigned long long* red = (unsigned long long*)(smem + RED_OFF);

    const int t = threadIdx.x;
    const int w = t >> 5, lane = t & 31;
    const int gid = lane >> 2, tig = lane & 3;
    const int wm = w & 1, wn = w >> 1;     // warp tile: rows wm*64, cols wn*64
    const int row0 = blockIdx.x * BM;
    const int jt0 = blockIdx.y * 43;
    const int jt1 = (jt0 + 43 < JT_TOTAL) ? jt0 + 43 : JT_TOTAL;

    float xnA[4], xnB[4];
#pragma unroll
    for (int i = 0; i < 4; i++) {
        xnA[i] = g_xnorm[row0 + wm * 64 + i * 16 + gid];
        xnB[i] = g_xnorm[row0 + wm * 64 + i * 16 + gid + 8];
    }

    unsigned long long bestA[4], bestB[4];
#pragma unroll
    for (int i = 0; i < 4; i++) bestA[i] = bestB[i] = 0xFFFFFFFFFFFFFFFFull;

    for (int jt = jt0; jt < jt1; jt++) {
        const int j0 = jt * BN;

        float acc[4][8][4];
#pragma unroll
        for (int i = 0; i < 4; i++)
#pragma unroll
            for (int j = 0; j < 8; j++)
#pragma unroll
                for (int q = 0; q < 4; q++) acc[i][j][q] = 0.f;

        load_stage(sb, 0, row0, j0, 0, t);
        CP_COMMIT();

        for (int s = 0; s < NSTAGE_K; s++) {
            if (s + 1 < NSTAGE_K) {
                load_stage(sb, (s + 1) & 1, row0, j0, s + 1, t);
                CP_COMMIT();
                CP_WAIT1();
            } else {
                CP_WAIT0();
            }
            __syncthreads();
            const uint32_t st  = sb + (s & 1) * STAGE_BYTES;
            const uint32_t sAh = st + OFF_AH, sAl = st + OFF_AL;
            const uint32_t sB  = st + OFF_B;

#pragma unroll
            for (int kk = 0; kk < BK / 16; kk++) {
                const int kb = kk * 32;   // bytes
                uint32_t Ah[4][4], Al[4][4], Bf[8][2];
#pragma unroll
                for (int jj = 0; jj < 4; jj++) {
                    uint32_t f[4];
                    ldmB4(sB, wn * 64 + jj * 16, kb, lane, f);
                    Bf[2 * jj][0] = f[0]; Bf[2 * jj][1] = f[1];
                    Bf[2 * jj + 1][0] = f[2]; Bf[2 * jj + 1][1] = f[3];
                }
#pragma unroll
                for (int i = 0; i < 4; i++)
                    ldmA(sAh, wm * 64 + i * 16, kb, lane, Ah[i]);
#pragma unroll
                for (int i = 0; i < 4; i++)
                    ldmA(sAl, wm * 64 + i * 16, kb, lane, Al[i]);
#pragma unroll
                for (int i = 0; i < 4; i++)
#pragma unroll
                    for (int j = 0; j < 8; j++)
                        mma_f16(acc[i][j], Ah[i], Bf[j]);   // hi * B
#pragma unroll
                for (int i = 0; i < 4; i++)
#pragma unroll
                    for (int j = 0; j < 8; j++)
                        mma_f16(acc[i][j], Al[i], Bf[j]);   // lo * B
            }
            __syncthreads();
        }

        // fold this j-tile into running per-thread mins
        float yn0[8], yn1[8];
#pragma unroll
        for (int j = 0; j < 8; j++) {
            int c = j0 + wn * 64 + j * 8 + tig * 2;
            yn0[j] = g_ynorm[c];
            yn1[j] = g_ynorm[c + 1];
        }
#pragma unroll
        for (int i = 0; i < 4; i++)
#pragma unroll
            for (int j = 0; j < 8; j++) {
                int c = j0 + wn * 64 + j * 8 + tig * 2;
                fold_min(bestA[i], xnA[i], yn0[j], acc[i][j][0], c);
                fold_min(bestA[i], xnA[i], yn1[j], acc[i][j][1], c + 1);
                fold_min(bestB[i], xnB[i], yn0[j], acc[i][j][2], c);
                fold_min(bestB[i], xnB[i], yn1[j], acc[i][j][3], c + 1);
            }
    }

    // reduce across tig lanes (same row, different cols)
#pragma unroll
    for (int i = 0; i < 4; i++) {
#pragma unroll
        for (int off = 1; off <= 2; off <<= 1) {
            unsigned long long va = __shfl_xor_sync(0xFFFFFFFFu, bestA[i], off);
            unsigned long long vb = __shfl_xor_sync(0xFFFFFFFFu, bestB[i], off);
            bestA[i] = (va < bestA[i]) ? va : bestA[i];
            bestB[i] = (vb < bestB[i]) ? vb : bestB[i];
        }
    }

    if (t < BM) red[t] = 0xFFFFFFFFFFFFFFFFull;
    __syncthreads();
    if (tig == 0) {
#pragma unroll
        for (int i = 0; i < 4; i++) {
            atomicMin(&red[wm * 64 + i * 16 + gid], bestA[i]);
            atomicMin(&red[wm * 64 + i * 16 + gid + 8], bestB[i]);
        }
    }
    __syncthreads();
    if (t < BM) atomicMin(&g_packed[row0 + t], red[t]);
}

// ---------------- tail kernels ----------------
__global__ void batch_reduce_kernel() {
    int b = blockIdx.x, t = threadIdx.x;
    __shared__ float sv[256];
    __shared__ int   si[256];
    float bv = -1.f; int bi = PATCHES;
    for (int p = t; p < PATCHES; p += 256) {
        unsigned long long pk = g_packed[b * PATCHES + p];
        float d = __uint_as_float((unsigned)(pk >> 32));
        if (d > bv || (d == bv && p < bi)) { bv = d; bi = p; }
    }
    sv[t] = bv; si[t] = bi;
    __syncthreads();
    for (int s = 128; s; s >>= 1) {
        if (t < s) {
            if (sv[t + s] > sv[t] || (sv[t + s] == sv[t] && si[t + s] < si[t])) {
                sv[t] = sv[t + s]; si[t] = si[t + s];
            }
        }
        __syncthreads();
    }
    if (t == 0) {
        int row = b * PATCHES + si[0];
        unsigned long long pk = g_packed[row];
        g_maxrow[b] = row;
        g_score[b]  = sqrtf(__uint_as_float((unsigned)(pk >> 32)));
        g_nnidx[b]  = (int)(pk & 0xFFFFFFFFull);
    }
}

__global__ void write_map_kernel(float* __restrict__ out) {
    int i = blockIdx.x * blockDim.x + threadIdx.x;
    if (i < N_ROWS)
        out[i] = sqrtf(__uint_as_float((unsigned)(g_packed[i] >> 32)));
}

__global__ void d2_kernel(const float* __restrict__ MB) {
    int b = blockIdx.y;
    int wid = threadIdx.x >> 5, lane = threadIdx.x & 31;
    int m = blockIdx.x * 8 + wid;
    int nn = g_nnidx[b];
    const float* pn = MB + (size_t)nn * DIM;
    const float* pm = MB + (size_t)m * DIM;
    float s = 0.f;
    for (int k = lane; k < DIM; k += 32) s += pn[k] * pm[k];
    s = warp_sum(s);
    if (!lane)
        g_d2[b * M_BANK + m] = fmaxf(g_ynorm[nn] + g_ynorm[m] - 2.f * s, 0.f);
}

__global__ void topk_kernel() {
    int b = blockIdx.x, t = threadIdx.x;
    __shared__ float sv[256];
    __shared__ int   si[256];
    __shared__ int   sel[KNN];
    for (int r = 0; r < KNN; r++) {
        float bv = FLT_MAX; int bi = M_BANK;
        for (int m = t; m < M_BANK; m += 256) {
            float v = g_d2[b * M_BANK + m];
            bool excl = false;
            for (int q = 0; q < r; q++) if (sel[q] == m) excl = true;
            if (!excl && (v < bv || (v == bv && m < bi))) { bv = v; bi = m; }
        }
        sv[t] = bv; si[t] = bi;
        __syncthreads();
        for (int s = 128; s; s >>= 1) {
            if (t < s) {
                if (sv[t + s] < sv[t] || (sv[t + s] == sv[t] && si[t + s] < si[t])) {
                    sv[t] = sv[t + s]; si[t] = si[t + s];
                }
            }
            __syncthreads();
        }
        if (t == 0) { sel[r] = si[0]; g_support[b * KNN + r] = si[0]; }
        __syncthreads();
    }
}

__global__ void final_kernel(const float* __restrict__ E,
                             const float* __restrict__ MB,
                             float* __restrict__ out) {
    int b = blockIdx.x;
    int wid = threadIdx.x >> 5, lane = threadIdx.x & 31;
    __shared__ float d3[KNN];
    int row = g_maxrow[b];
    const float* xf = E + (size_t)row * DIM;
    int sup = g_support[b * KNN + wid];
    const float* pv = MB + (size_t)sup * DIM;
    float s = 0.f;
    for (int k = lane; k < DIM; k += 32) s += xf[k] * pv[k];
    s = warp_sum(s);
    if (!lane)
        d3[wid] = sqrtf(fmaxf(g_xnorm[row] + g_ynorm[sup] - 2.f * s, 0.f));
    __syncthreads();
    if (threadIdx.x == 0) {
        float mx = -FLT_MAX;
        for (int j = 0; j < KNN; j++) mx = fmaxf(mx, d3[j]);
        float den = 0.f, e0 = 0.f;
        for (int j = 0; j < KNN; j++) {
            float e = expf(d3[j] - mx);
            den += e;
            if (j == 0) e0 = e;
        }
        out[N_ROWS + b] = (1.f - e0 / den) * g_score[b];
    }
}

// ---------------- launch ----------------
extern "C" void kernel_launch(void* const* d_in, const int* in_sizes, int n_in,
                              void* d_out, int out_size) {
    (void)n_in; (void)in_sizes; (void)out_size;
    const float* E  = (const float*)d_in[0];
    const float* MB = (const float*)d_in[1];
    float* out = (float*)d_out;

    cudaFuncSetAttribute(gemm_mma_kernel,
                         cudaFuncAttributeMaxDynamicSharedMemorySize, SMEM_BYTES);

    split_kernel<<<(N_ROWS * DIM + 255) / 256, 256>>>(E, 0);
    split_kernel<<<(M_BANK * DIM + 255) / 256, 256>>>(MB, 1);
    init_packed_kernel<<<(N_ROWS + 255) / 256, 256>>>();
    norms_kernel<<<(N_ROWS * 32 + 255) / 256, 256>>>(E, N_ROWS, 0);
    norms_kernel<<<(M_BANK * 32 + 255) / 256, 256>>>(MB, M_BANK, 1);

    gemm_mma_kernel<<<dim3(ROW_TILES, GRID_Y), 256, SMEM_BYTES>>>();

    batch_reduce_kernel<<<B_SZ, 256>>>();
    write_map_kernel<<<(N_ROWS + 255) / 256, 256>>>(out);
    d2_kernel<<<dim3(M_BANK / 8, B_SZ), 256>>>(MB);
    topk_kernel<<<B_SZ, 256>>>();
    final_kernel<<<B_SZ, KNN * 32>>>(E, MB, out);
}

// round 5
// speedup vs baseline: 8.9505x; 1.5557x over previous
#include <cuda_runtime.h>
#include <cuda_fp16.h>
#include <float.h>
#include <stdint.h>

// ---------------- problem constants ----------------
constexpr int N_ROWS  = 6272;
constexpr int M_BANK  = 32768;
constexpr int DIM     = 384;
constexpr int B_SZ    = 8;
constexpr int PATCHES = N_ROWS / B_SZ;
constexpr int KNN     = 9;

// ---------------- GEMM tiling ----------------
constexpr int BM = 128;
constexpr int BN = 256;
constexpr int BK = 64;                 // halves per chunk = 128 bytes/row
constexpr int NCHUNK_K = DIM / BK;     // 6
constexpr int JT_TOTAL = M_BANK / BN;  // 128
constexpr int GRID_Y   = 3;            // 43+43+42 j-tiles -> 147 CTAs = 1 wave
constexpr int ROW_TILES = N_ROWS / BM; // 49

// SMEM layout (bytes): A-full (6 chunks x 16KB) + 4 B stages x 32KB + reduce
constexpr int A_CHUNK_BYTES = BM * 128;            // 16384
constexpr int OFF_B         = NCHUNK_K * A_CHUNK_BYTES;   // 98304
constexpr int B_STAGE_BYTES = BN * 128;            // 32768
constexpr int RED_OFF       = OFF_B + 4 * B_STAGE_BYTES;  // 229376
constexpr int SMEM_BYTES    = RED_OFF + BM * 8;           // 230400

// ---------------- device scratch ----------------
__device__ __align__(256) __half g_Eh[N_ROWS * DIM];
__device__ __align__(256) __half g_Bh[M_BANK * DIM];
__device__ float              g_xnorm[N_ROWS];
__device__ float              g_ynorm[M_BANK];
__device__ unsigned long long g_packed[N_ROWS];
__device__ float              g_d2[B_SZ * M_BANK];
__device__ int                g_support[B_SZ * KNN];
__device__ int                g_maxrow[B_SZ];
__device__ float              g_score[B_SZ];
__device__ int                g_nnidx[B_SZ];

// ---------------- helpers ----------------
__device__ __forceinline__ uint32_t smem_u32(const void* p) {
    uint32_t a;
    asm("{ .reg .u64 t; cvta.to.shared.u64 t, %1; cvt.u32.u64 %0, t; }"
        : "=r"(a) : "l"(p));
    return a;
}
__device__ __forceinline__ void cp16(uint32_t dst, const void* src) {
    asm volatile("cp.async.cg.shared.global [%0], [%1], 16;"
                 :: "r"(dst), "l"(src) : "memory");
}
#define CP_COMMIT() asm volatile("cp.async.commit_group;" ::: "memory")
#define CP_WAIT2()  asm volatile("cp.async.wait_group 2;" ::: "memory")

__device__ __forceinline__ uint32_t swz(uint32_t o) { return o ^ ((o >> 3) & 0x70); }

__device__ __forceinline__ void ldmA(uint32_t base, int r_base, int kb,
                                     int lane, uint32_t* f) {
    int q = lane >> 3;
    int r = r_base + (q & 1) * 8 + (lane & 7);
    int kk = kb + (q >> 1) * 16;
    uint32_t a = base + swz((uint32_t)(r * 128 + kk));
    asm volatile("ldmatrix.sync.aligned.m8n8.x4.shared.b16 {%0,%1,%2,%3}, [%4];"
                 : "=r"(f[0]), "=r"(f[1]), "=r"(f[2]), "=r"(f[3]) : "r"(a));
}
__device__ __forceinline__ void ldmB4(uint32_t base, int n_base, int kb,
                                      int lane, uint32_t* f) {
    int q = lane >> 3;
    int n = n_base + (q >> 1) * 8 + (lane & 7);
    int kk = kb + (q & 1) * 16;
    uint32_t a = base + swz((uint32_t)(n * 128 + kk));
    asm volatile("ldmatrix.sync.aligned.m8n8.x4.shared.b16 {%0,%1,%2,%3}, [%4];"
                 : "=r"(f[0]), "=r"(f[1]), "=r"(f[2]), "=r"(f[3]) : "r"(a));
}
__device__ __forceinline__ void mma_f16(float* c, const uint32_t* a,
                                        const uint32_t* b) {
    asm volatile(
        "mma.sync.aligned.m16n8k16.row.col.f32.f16.f16.f32 "
        "{%0,%1,%2,%3},{%4,%5,%6,%7},{%8,%9},{%0,%1,%2,%3};"
        : "+f"(c[0]), "+f"(c[1]), "+f"(c[2]), "+f"(c[3])
        : "r"(a[0]), "r"(a[1]), "r"(a[2]), "r"(a[3]), "r"(b[0]), "r"(b[1]));
}
__device__ __forceinline__ float warp_sum(float s) {
#pragma unroll
    for (int o = 16; o; o >>= 1) s += __shfl_xor_sync(0xFFFFFFFFu, s, o);
    return s;
}
__device__ __forceinline__ void fold_min(unsigned long long& best, float xn,
                                         float yn, float dot, int col) {
    float d = fmaxf(fmaf(-2.f, dot, xn + yn), 0.f);
    unsigned long long p =
        ((unsigned long long)__float_as_uint(d) << 32) | (unsigned)col;
    best = (p < best) ? p : best;
}

// ---------------- fused prep: fp16 convert + row norms ----------------
// one warp per row: 12 floats per lane (3 float4 loads, 6 half2 stores)
__global__ void prep_kernel(const float* __restrict__ X, int rows, int which) {
    int warp = (blockIdx.x * blockDim.x + threadIdx.x) >> 5;
    int lane = threadIdx.x & 31;
    if (warp >= rows) return;
    const float4* p =
        reinterpret_cast<const float4*>(X + (size_t)warp * DIM + lane * 12);
    __half2* dst = reinterpret_cast<__half2*>(
        (which ? g_Bh : g_Eh) + (size_t)warp * DIM + lane * 12);
    float s = 0.f;
#pragma unroll
    for (int v = 0; v < 3; v++) {
        float4 f = p[v];
        s += f.x * f.x + f.y * f.y + f.z * f.z + f.w * f.w;
        dst[v * 2]     = __floats2half2_rn(f.x, f.y);
        dst[v * 2 + 1] = __floats2half2_rn(f.z, f.w);
    }
    s = warp_sum(s);
    if (!lane) { if (which) g_ynorm[warp] = s; else g_xnorm[warp] = s; }
}

__global__ void init_packed_kernel() {
    int i = blockIdx.x * blockDim.x + threadIdx.x;
    if (i < N_ROWS) g_packed[i] = 0xFFFFFFFFFFFFFFFFull;
}

// ---------------- B chunk loader ----------------
__device__ __forceinline__ void load_B(uint32_t sb, int c, int jt0, int t) {
    uint32_t sbase = sb + OFF_B + (c & 3) * B_STAGE_BYTES;
    int j0  = (jt0 + c / NCHUNK_K) * BN;
    int kof = (c % NCHUNK_K) * BK;
#pragma unroll 8
    for (int i = t; i < BN * 8; i += 256) {
        int r = i >> 3, g = i & 7;
        uint32_t d = swz((uint32_t)(r * 128 + g * 16));
        cp16(sbase + d, g_Bh + (size_t)(j0 + r) * DIM + kof + g * 8);
    }
}

// ---------------- main GEMM + fused min/argmin ----------------
__global__ __launch_bounds__(256, 1) void gemm_mma_kernel() {
    extern __shared__ __align__(1024) char smem[];
    uint32_t sb = smem_u32(smem);
    unsigned long long* red = (unsigned long long*)(smem + RED_OFF);

    const int t = threadIdx.x;
    const int w = t >> 5, lane = t & 31;
    const int gid = lane >> 2, tig = lane & 3;
    const int wm = w & 1, wn = w >> 1;     // warp tile: rows wm*64, cols wn*64
    const int row0 = blockIdx.x * BM;
    const int jt0 = blockIdx.y * 43;
    const int jt1 = (jt0 + 43 < JT_TOTAL) ? jt0 + 43 : JT_TOTAL;
    const int TOT = (jt1 - jt0) * NCHUNK_K;

    float xnA[4], xnB[4];
#pragma unroll
    for (int i = 0; i < 4; i++) {
        xnA[i] = g_xnorm[row0 + wm * 64 + i * 16 + gid];
        xnB[i] = g_xnorm[row0 + wm * 64 + i * 16 + gid + 8];
    }

    unsigned long long bestA[4], bestB[4];
#pragma unroll
    for (int i = 0; i < 4; i++) bestA[i] = bestB[i] = 0xFFFFFFFFFFFFFFFFull;

    // prologue: A full-K resident load (group 0)
#pragma unroll 2
    for (int ck = 0; ck < NCHUNK_K; ck++) {
        for (int i = t; i < BM * 8; i += 256) {
            int r = i >> 3, g = i & 7;
            uint32_t d = swz((uint32_t)(r * 128 + g * 16));
            cp16(sb + ck * A_CHUNK_BYTES + d,
                 g_Eh + (size_t)(row0 + r) * DIM + ck * BK + g * 8);
        }
    }
    CP_COMMIT();
    // preload B chunks 0..2 (groups 1..3)
    for (int p = 0; p < 3; p++) { load_B(sb, p, jt0, t); CP_COMMIT(); }

    float acc[4][8][4];
#pragma unroll
    for (int i = 0; i < 4; i++)
#pragma unroll
        for (int j = 0; j < 8; j++)
#pragma unroll
            for (int q = 0; q < 4; q++) acc[i][j][q] = 0.f;

    for (int c = 0; c < TOT; c++) {
        CP_WAIT2();            // chunk c (and A) now resident
        __syncthreads();
        if (c + 3 < TOT) load_B(sb, c + 3, jt0, t);
        CP_COMMIT();           // empty group in tail keeps count uniform

        const int ck = c % NCHUNK_K;
        const uint32_t sA = sb + ck * A_CHUNK_BYTES;
        const uint32_t sB = sb + OFF_B + (c & 3) * B_STAGE_BYTES;

#pragma unroll
        for (int kk = 0; kk < BK / 16; kk++) {
            const int kb = kk * 32;   // bytes
            uint32_t Af[4][4], Bf[8][2];
#pragma unroll
            for (int jj = 0; jj < 4; jj++) {
                uint32_t f[4];
                ldmB4(sB, wn * 64 + jj * 16, kb, lane, f);
                Bf[2 * jj][0] = f[0]; Bf[2 * jj][1] = f[1];
                Bf[2 * jj + 1][0] = f[2]; Bf[2 * jj + 1][1] = f[3];
            }
#pragma unroll
            for (int i = 0; i < 4; i++)
                ldmA(sA, wm * 64 + i * 16, kb, lane, Af[i]);
#pragma unroll
            for (int i = 0; i < 4; i++)
#pragma unroll
                for (int j = 0; j < 8; j++)
                    mma_f16(acc[i][j], Af[i], Bf[j]);
        }

        if (ck == NCHUNK_K - 1) {
            // j-tile done: fold into running per-thread mins, reset acc
            const int j0 = (jt0 + c / NCHUNK_K) * BN;
            float yn0[8], yn1[8];
#pragma unroll
            for (int j = 0; j < 8; j++) {
                int col = j0 + wn * 64 + j * 8 + tig * 2;
                yn0[j] = g_ynorm[col];
                yn1[j] = g_ynorm[col + 1];
            }
#pragma unroll
            for (int i = 0; i < 4; i++)
#pragma unroll
                for (int j = 0; j < 8; j++) {
                    int col = j0 + wn * 64 + j * 8 + tig * 2;
                    fold_min(bestA[i], xnA[i], yn0[j], acc[i][j][0], col);
                    fold_min(bestA[i], xnA[i], yn1[j], acc[i][j][1], col + 1);
                    fold_min(bestB[i], xnB[i], yn0[j], acc[i][j][2], col);
                    fold_min(bestB[i], xnB[i], yn1[j], acc[i][j][3], col + 1);
                    acc[i][j][0] = acc[i][j][1] = acc[i][j][2] = acc[i][j][3] = 0.f;
                }
        }
    }

    // reduce across tig lanes (same row, different cols)
#pragma unroll
    for (int i = 0; i < 4; i++) {
#pragma unroll
        for (int off = 1; off <= 2; off <<= 1) {
            unsigned long long va = __shfl_xor_sync(0xFFFFFFFFu, bestA[i], off);
            unsigned long long vb = __shfl_xor_sync(0xFFFFFFFFu, bestB[i], off);
            bestA[i] = (va < bestA[i]) ? va : bestA[i];
            bestB[i] = (vb < bestB[i]) ? vb : bestB[i];
        }
    }

    if (t < BM) red[t] = 0xFFFFFFFFFFFFFFFFull;
    __syncthreads();
    if (tig == 0) {
#pragma unroll
        for (int i = 0; i < 4; i++) {
            atomicMin(&red[wm * 64 + i * 16 + gid], bestA[i]);
            atomicMin(&red[wm * 64 + i * 16 + gid + 8], bestB[i]);
        }
    }
    __syncthreads();
    if (t < BM) atomicMin(&g_packed[row0 + t], red[t]);
}

// ---------------- tail kernels ----------------
__global__ void batch_reduce_kernel() {
    int b = blockIdx.x, t = threadIdx.x;
    __shared__ float sv[256];
    __shared__ int   si[256];
    float bv = -1.f; int bi = PATCHES;
    for (int p = t; p < PATCHES; p += 256) {
        unsigned long long pk = g_packed[b * PATCHES + p];
        float d = __uint_as_float((unsigned)(pk >> 32));
        if (d > bv || (d == bv && p < bi)) { bv = d; bi = p; }
    }
    sv[t] = bv; si[t] = bi;
    __syncthreads();
    for (int s = 128; s; s >>= 1) {
        if (t < s) {
            if (sv[t + s] > sv[t] || (sv[t + s] == sv[t] && si[t + s] < si[t])) {
                sv[t] = sv[t + s]; si[t] = si[t + s];
            }
        }
        __syncthreads();
    }
    if (t == 0) {
        int row = b * PATCHES + si[0];
        unsigned long long pk = g_packed[row];
        g_maxrow[b] = row;
        g_score[b]  = sqrtf(__uint_as_float((unsigned)(pk >> 32)));
        g_nnidx[b]  = (int)(pk & 0xFFFFFFFFull);
    }
}

__global__ void write_map_kernel(float* __restrict__ out) {
    int i = blockIdx.x * blockDim.x + threadIdx.x;
    if (i < N_ROWS)
        out[i] = sqrtf(__uint_as_float((unsigned)(g_packed[i] >> 32)));
}

__global__ void d2_kernel(const float* __restrict__ MB) {
    int b = blockIdx.y;
    int wid = threadIdx.x >> 5, lane = threadIdx.x & 31;
    int m = blockIdx.x * 8 + wid;
    int nn = g_nnidx[b];
    const float* pn = MB + (size_t)nn * DIM;
    const float* pm = MB + (size_t)m * DIM;
    float s = 0.f;
    for (int k = lane; k < DIM; k += 32) s += pn[k] * pm[k];
    s = warp_sum(s);
    if (!lane)
        g_d2[b * M_BANK + m] = fmaxf(g_ynorm[nn] + g_ynorm[m] - 2.f * s, 0.f);
}

__global__ void topk_kernel() {
    int b = blockIdx.x, t = threadIdx.x;
    __shared__ float sv[256];
    __shared__ int   si[256];
    __shared__ int   sel[KNN];
    for (int r = 0; r < KNN; r++) {
        float bv = FLT_MAX; int bi = M_BANK;
        for (int m = t; m < M_BANK; m += 256) {
            float v = g_d2[b * M_BANK + m];
            bool excl = false;
            for (int q = 0; q < r; q++) if (sel[q] == m) excl = true;
            if (!excl && (v < bv || (v == bv && m < bi))) { bv = v; bi = m; }
        }
        sv[t] = bv; si[t] = bi;
        __syncthreads();
        for (int s = 128; s; s >>= 1) {
            if (t < s) {
                if (sv[t + s] < sv[t] || (sv[t + s] == sv[t] && si[t + s] < si[t])) {
                    sv[t] = sv[t + s]; si[t] = si[t + s];
                }
            }
            __syncthreads();
        }
        if (t == 0) { sel[r] = si[0]; g_support[b * KNN + r] = si[0]; }
        __syncthreads();
    }
}

__global__ void final_kernel(const float* __restrict__ E,
                             const float* __restrict__ MB,
                             float* __restrict__ out) {
    int b = blockIdx.x;
    int wid = threadIdx.x >> 5, lane = threadIdx.x & 31;
    __shared__ float d3[KNN];
    int row = g_maxrow[b];
    const float* xf = E + (size_t)row * DIM;
    int sup = g_support[b * KNN + wid];
    const float* pv = MB + (size_t)sup * DIM;
    float s = 0.f;
    for (int k = lane; k < DIM; k += 32) s += xf[k] * pv[k];
    s = warp_sum(s);
    if (!lane)
        d3[wid] = sqrtf(fmaxf(g_xnorm[row] + g_ynorm[sup] - 2.f * s, 0.f));
    __syncthreads();
    if (threadIdx.x == 0) {
        float mx = -FLT_MAX;
        for (int j = 0; j < KNN; j++) mx = fmaxf(mx, d3[j]);
        float den = 0.f, e0 = 0.f;
        for (int j = 0; j < KNN; j++) {
            float e = expf(d3[j] - mx);
            den += e;
            if (j == 0) e0 = e;
        }
        out[N_ROWS + b] = (1.f - e0 / den) * g_score[b];
    }
}

// ---------------- launch ----------------
extern "C" void kernel_launch(void* const* d_in, const int* in_sizes, int n_in,
                              void* d_out, int out_size) {
    (void)n_in; (void)in_sizes; (void)out_size;
    const float* E  = (const float*)d_in[0];
    const float* MB = (const float*)d_in[1];
    float* out = (float*)d_out;

    cudaFuncSetAttribute(gemm_mma_kernel,
                         cudaFuncAttributeMaxDynamicSharedMemorySize, SMEM_BYTES);

    prep_kernel<<<(N_ROWS * 32 + 255) / 256, 256>>>(E, N_ROWS, 0);
    prep_kernel<<<(M_BANK * 32 + 255) / 256, 256>>>(MB, M_BANK, 1);
    init_packed_kernel<<<(N_ROWS + 255) / 256, 256>>>();

    gemm_mma_kernel<<<dim3(ROW_TILES, GRID_Y), 256, SMEM_BYTES>>>();

    batch_reduce_kernel<<<B_SZ, 256>>>();
    write_map_kernel<<<(N_ROWS + 255) / 256, 256>>>(out);
    d2_kernel<<<dim3(M_BANK / 8, B_SZ), 256>>>(MB);
    topk_kernel<<<B_SZ, 256>>>();
    final_kernel<<<B_SZ, KNN * 32>>>(E, MB, out);
}

// round 6
// speedup vs baseline: 11.6757x; 1.3045x over previous
#include <cuda_runtime.h>
#include <cuda_fp16.h>
#include <float.h>
#include <stdint.h>

// ---------------- problem constants ----------------
constexpr int N_ROWS  = 6272;
constexpr int M_BANK  = 32768;
constexpr int DIM     = 384;
constexpr int B_SZ    = 8;
constexpr int PATCHES = N_ROWS / B_SZ;
constexpr int KNN     = 9;

// ---------------- GEMM tiling ----------------
constexpr int BM = 128;
constexpr int BN = 256;
constexpr int BK = 64;                 // halves per chunk = 128 bytes/row
constexpr int NCHUNK_K = DIM / BK;     // 6
constexpr int JT_TOTAL = M_BANK / BN;  // 128
constexpr int GRID_Y   = 3;            // 147 CTAs = 1 wave
constexpr int ROW_TILES = N_ROWS / BM; // 49
constexpr int NTHR = 512;              // 16 warps

// SMEM: A-full (6 x 16KB) + 4 B stages x 32KB + reduce
constexpr int A_CHUNK_BYTES = BM * 128;                   // 16384
constexpr int OFF_B         = NCHUNK_K * A_CHUNK_BYTES;   // 98304
constexpr int B_STAGE_BYTES = BN * 128;                   // 32768
constexpr int RED_OFF       = OFF_B + 4 * B_STAGE_BYTES;  // 229376
constexpr int SMEM_BYTES    = RED_OFF + BM * 8;           // 230400

// top-k staging
constexpr int SEGS = 32;
constexpr int SEG_LEN = M_BANK / SEGS;  // 1024

// ---------------- device scratch ----------------
__device__ __align__(256) __half g_Eh[N_ROWS * DIM];
__device__ __align__(256) __half g_Bh[M_BANK * DIM];
__device__ float              g_xnorm[N_ROWS];
__device__ float              g_ynorm[M_BANK];
__device__ unsigned long long g_packed[N_ROWS];
__device__ float              g_d2[B_SZ * M_BANK];
__device__ unsigned long long g_part[B_SZ * SEGS * KNN];
__device__ int                g_support[B_SZ * KNN];
__device__ int                g_maxrow[B_SZ];
__device__ float              g_score[B_SZ];
__device__ int                g_nnidx[B_SZ];

// ---------------- helpers ----------------
__device__ __forceinline__ uint32_t smem_u32(const void* p) {
    uint32_t a;
    asm("{ .reg .u64 t; cvta.to.shared.u64 t, %1; cvt.u32.u64 %0, t; }"
        : "=r"(a) : "l"(p));
    return a;
}
__device__ __forceinline__ void cp16(uint32_t dst, const void* src) {
    asm volatile("cp.async.cg.shared.global [%0], [%1], 16;"
                 :: "r"(dst), "l"(src) : "memory");
}
#define CP_COMMIT() asm volatile("cp.async.commit_group;" ::: "memory")
#define CP_WAIT2()  asm volatile("cp.async.wait_group 2;" ::: "memory")

__device__ __forceinline__ uint32_t swz(uint32_t o) { return o ^ ((o >> 3) & 0x70); }

__device__ __forceinline__ void ldmA(uint32_t base, int r_base, int kb,
                                     int lane, uint32_t* f) {
    int q = lane >> 3;
    int r = r_base + (q & 1) * 8 + (lane & 7);
    int kk = kb + (q >> 1) * 16;
    uint32_t a = base + swz((uint32_t)(r * 128 + kk));
    asm volatile("ldmatrix.sync.aligned.m8n8.x4.shared.b16 {%0,%1,%2,%3}, [%4];"
                 : "=r"(f[0]), "=r"(f[1]), "=r"(f[2]), "=r"(f[3]) : "r"(a));
}
__device__ __forceinline__ void ldmB4(uint32_t base, int n_base, int kb,
                                      int lane, uint32_t* f) {
    int q = lane >> 3;
    int n = n_base + (q >> 1) * 8 + (lane & 7);
    int kk = kb + (q & 1) * 16;
    uint32_t a = base + swz((uint32_t)(n * 128 + kk));
    asm volatile("ldmatrix.sync.aligned.m8n8.x4.shared.b16 {%0,%1,%2,%3}, [%4];"
                 : "=r"(f[0]), "=r"(f[1]), "=r"(f[2]), "=r"(f[3]) : "r"(a));
}
__device__ __forceinline__ void mma_f16(float* c, const uint32_t* a,
                                        const uint32_t* b) {
    asm volatile(
        "mma.sync.aligned.m16n8k16.row.col.f32.f16.f16.f32 "
        "{%0,%1,%2,%3},{%4,%5,%6,%7},{%8,%9},{%0,%1,%2,%3};"
        : "+f"(c[0]), "+f"(c[1]), "+f"(c[2]), "+f"(c[3])
        : "r"(a[0]), "r"(a[1]), "r"(a[2]), "r"(a[3]), "r"(b[0]), "r"(b[1]));
}
__device__ __forceinline__ float warp_sum(float s) {
#pragma unroll
    for (int o = 16; o; o >>= 1) s += __shfl_xor_sync(0xFFFFFFFFu, s, o);
    return s;
}
__device__ __forceinline__ unsigned long long umin64(unsigned long long a,
                                                     unsigned long long b) {
    return a < b ? a : b;
}
__device__ __forceinline__ void fold_min(unsigned long long& best, float xn,
                                         float yn, float dot, int col) {
    float d = fmaxf(fmaf(-2.f, dot, xn + yn), 0.f);
    unsigned long long p =
        ((unsigned long long)__float_as_uint(d) << 32) | (unsigned)col;
    best = umin64(best, p);
}

// ---------------- fused prep: fp16 convert + norms + packed init ----------------
__global__ void prep_all_kernel(const float* __restrict__ E,
                                const float* __restrict__ MB) {
    int warp = (blockIdx.x * blockDim.x + threadIdx.x) >> 5;
    int lane = threadIdx.x & 31;
    if (warp >= N_ROWS + M_BANK) return;
    bool isE = warp < N_ROWS;
    int row = isE ? warp : warp - N_ROWS;
    const float* src = isE ? E : MB;
    __half* dsth = isE ? g_Eh : g_Bh;
    const float4* p =
        reinterpret_cast<const float4*>(src + (size_t)row * DIM + lane * 12);
    __half2* dst =
        reinterpret_cast<__half2*>(dsth + (size_t)row * DIM + lane * 12);
    float s = 0.f;
#pragma unroll
    for (int v = 0; v < 3; v++) {
        float4 f = p[v];
        s += f.x * f.x + f.y * f.y + f.z * f.z + f.w * f.w;
        dst[v * 2]     = __floats2half2_rn(f.x, f.y);
        dst[v * 2 + 1] = __floats2half2_rn(f.z, f.w);
    }
    s = warp_sum(s);
    if (!lane) {
        if (isE) { g_xnorm[row] = s; g_packed[row] = 0xFFFFFFFFFFFFFFFFull; }
        else     g_ynorm[row] = s;
    }
}

// ---------------- B chunk loader ----------------
__device__ __forceinline__ void load_B(uint32_t sb, int c, int jt0, int t) {
    uint32_t sbase = sb + OFF_B + (c & 3) * B_STAGE_BYTES;
    int j0  = (jt0 + c / NCHUNK_K) * BN;
    int kof = (c % NCHUNK_K) * BK;
#pragma unroll 4
    for (int i = t; i < BN * 8; i += NTHR) {
        int r = i >> 3, g = i & 7;
        uint32_t d = swz((uint32_t)(r * 128 + g * 16));
        cp16(sbase + d, g_Bh + (size_t)(j0 + r) * DIM + kof + g * 8);
    }
}

// ---------------- main GEMM + fused min/argmin ----------------
__global__ __launch_bounds__(NTHR, 1) void gemm_mma_kernel() {
    extern __shared__ __align__(1024) char smem[];
    uint32_t sb = smem_u32(smem);
    unsigned long long* red = (unsigned long long*)(smem + RED_OFF);

    const int t = threadIdx.x;
    const int w = t >> 5, lane = t & 31;
    const int gid = lane >> 2, tig = lane & 3;
    const int wm = w & 1, wn = w >> 1;     // warp tile: rows wm*64(+64), cols wn*32
    const int row0 = blockIdx.x * BM;
    const int jt0 = blockIdx.y * 43;
    const int jt1 = (jt0 + 43 < JT_TOTAL) ? jt0 + 43 : JT_TOTAL;
    const int TOT = (jt1 - jt0) * NCHUNK_K;

    float xnA[4], xnB[4];
#pragma unroll
    for (int i = 0; i < 4; i++) {
        xnA[i] = g_xnorm[row0 + wm * 64 + i * 16 + gid];
        xnB[i] = g_xnorm[row0 + wm * 64 + i * 16 + gid + 8];
    }

    unsigned long long bestA[4], bestB[4];
#pragma unroll
    for (int i = 0; i < 4; i++) bestA[i] = bestB[i] = 0xFFFFFFFFFFFFFFFFull;

    // prologue: A full-K resident (group 0)
#pragma unroll
    for (int ck = 0; ck < NCHUNK_K; ck++) {
        for (int i = t; i < BM * 8; i += NTHR) {
            int r = i >> 3, g = i & 7;
            uint32_t d = swz((uint32_t)(r * 128 + g * 16));
            cp16(sb + ck * A_CHUNK_BYTES + d,
                 g_Eh + (size_t)(row0 + r) * DIM + ck * BK + g * 8);
        }
    }
    CP_COMMIT();
    for (int p = 0; p < 3; p++) { load_B(sb, p, jt0, t); CP_COMMIT(); }

    float acc[4][4][4];
#pragma unroll
    for (int i = 0; i < 4; i++)
#pragma unroll
        for (int j = 0; j < 4; j++)
#pragma unroll
            for (int q = 0; q < 4; q++) acc[i][j][q] = 0.f;

    for (int c = 0; c < TOT; c++) {
        CP_WAIT2();
        __syncthreads();
        if (c + 3 < TOT) load_B(sb, c + 3, jt0, t);
        CP_COMMIT();

        const int ck = c % NCHUNK_K;
        const uint32_t sA = sb + ck * A_CHUNK_BYTES;
        const uint32_t sB = sb + OFF_B + (c & 3) * B_STAGE_BYTES;

#pragma unroll
        for (int kk = 0; kk < BK / 16; kk++) {
            const int kb = kk * 32;   // bytes
            uint32_t Af[4][4], Bf[4][2];
#pragma unroll
            for (int jj = 0; jj < 2; jj++) {
                uint32_t f[4];
                ldmB4(sB, wn * 32 + jj * 16, kb, lane, f);
                Bf[2 * jj][0] = f[0]; Bf[2 * jj][1] = f[1];
                Bf[2 * jj + 1][0] = f[2]; Bf[2 * jj + 1][1] = f[3];
            }
#pragma unroll
            for (int i = 0; i < 4; i++)
                ldmA(sA, wm * 64 + i * 16, kb, lane, Af[i]);
#pragma unroll
            for (int i = 0; i < 4; i++)
#pragma unroll
                for (int j = 0; j < 4; j++)
                    mma_f16(acc[i][j], Af[i], Bf[j]);
        }

        if (ck == NCHUNK_K - 1) {
            const int j0 = (jt0 + c / NCHUNK_K) * BN;
#pragma unroll
            for (int i = 0; i < 4; i++)
#pragma unroll
                for (int j = 0; j < 4; j++) {
                    int col = j0 + wn * 32 + j * 8 + tig * 2;
                    float yn0 = g_ynorm[col], yn1 = g_ynorm[col + 1];
                    fold_min(bestA[i], xnA[i], yn0, acc[i][j][0], col);
                    fold_min(bestA[i], xnA[i], yn1, acc[i][j][1], col + 1);
                    fold_min(bestB[i], xnB[i], yn0, acc[i][j][2], col);
                    fold_min(bestB[i], xnB[i], yn1, acc[i][j][3], col + 1);
                    acc[i][j][0] = acc[i][j][1] = acc[i][j][2] = acc[i][j][3] = 0.f;
                }
        }
    }

    // reduce across tig lanes (same row)
#pragma unroll
    for (int i = 0; i < 4; i++) {
#pragma unroll
        for (int off = 1; off <= 2; off <<= 1) {
            bestA[i] = umin64(bestA[i], __shfl_xor_sync(0xFFFFFFFFu, bestA[i], off));
            bestB[i] = umin64(bestB[i], __shfl_xor_sync(0xFFFFFFFFu, bestB[i], off));
        }
    }

    if (t < BM) red[t] = 0xFFFFFFFFFFFFFFFFull;
    __syncthreads();
    if (tig == 0) {
#pragma unroll
        for (int i = 0; i < 4; i++) {
            atomicMin(&red[wm * 64 + i * 16 + gid], bestA[i]);
            atomicMin(&red[wm * 64 + i * 16 + gid + 8], bestB[i]);
        }
    }
    __syncthreads();
    if (t < BM) atomicMin(&g_packed[row0 + t], red[t]);
}

// ---------------- tail: batch argmax ----------------
__global__ void batch_reduce_kernel() {
    int b = blockIdx.x, t = threadIdx.x;
    __shared__ float sv[256];
    __shared__ int   si[256];
    float bv = -1.f; int bi = PATCHES;
    for (int p = t; p < PATCHES; p += 256) {
        unsigned long long pk = g_packed[b * PATCHES + p];
        float d = __uint_as_float((unsigned)(pk >> 32));
        if (d > bv || (d == bv && p < bi)) { bv = d; bi = p; }
    }
    sv[t] = bv; si[t] = bi;
    __syncthreads();
    for (int s = 128; s; s >>= 1) {
        if (t < s) {
            if (sv[t + s] > sv[t] || (sv[t + s] == sv[t] && si[t + s] < si[t])) {
                sv[t] = sv[t + s]; si[t] = si[t + s];
            }
        }
        __syncthreads();
    }
    if (t == 0) {
        int row = b * PATCHES + si[0];
        unsigned long long pk = g_packed[row];
        g_maxrow[b] = row;
        g_score[b]  = sqrtf(__uint_as_float((unsigned)(pk >> 32)));
        g_nnidx[b]  = (int)(pk & 0xFFFFFFFFull);
    }
}

__global__ void write_map_kernel(float* __restrict__ out) {
    int i = blockIdx.x * blockDim.x + threadIdx.x;
    if (i < N_ROWS)
        out[i] = sqrtf(__uint_as_float((unsigned)(g_packed[i] >> 32)));
}

// ---------------- d2: bank read once, all 8 batches per pass ----------------
__global__ void d2_block_kernel(const float* __restrict__ MB) {
    __shared__ float4 nn4[B_SZ][DIM / 4];   // 12 KB
    __shared__ float  nyn[B_SZ];
    int t = threadIdx.x, wid = t >> 5, lane = t & 31;
    // load 8 nn rows
    for (int i = t; i < B_SZ * (DIM / 4); i += 256) {
        int b = i / (DIM / 4), v = i % (DIM / 4);
        nn4[b][v] = reinterpret_cast<const float4*>(
            MB + (size_t)g_nnidx[b] * DIM)[v];
    }
    if (t < B_SZ) nyn[t] = g_ynorm[g_nnidx[t]];
    __syncthreads();

    int m = blockIdx.x * 8 + wid;
    const float4* pm4 = reinterpret_cast<const float4*>(MB + (size_t)m * DIM);
    float s[B_SZ];
#pragma unroll
    for (int b = 0; b < B_SZ; b++) s[b] = 0.f;
#pragma unroll
    for (int v = 0; v < 3; v++) {
        float4 f = pm4[lane + v * 32];
#pragma unroll
        for (int b = 0; b < B_SZ; b++) {
            float4 g = nn4[b][lane + v * 32];
            s[b] += f.x * g.x + f.y * g.y + f.z * g.z + f.w * g.w;
        }
    }
#pragma unroll
    for (int b = 0; b < B_SZ; b++) s[b] = warp_sum(s[b]);
    if (lane == 0) {
        float ym = g_ynorm[m];
#pragma unroll
        for (int b = 0; b < B_SZ; b++)
            g_d2[b * M_BANK + m] = fmaxf(nyn[b] + ym - 2.f * s[b], 0.f);
    }
}

// ---------------- top-9 stage A: per-segment selection ----------------
__global__ void topkA_kernel() {
    __shared__ unsigned long long vals[SEG_LEN];
    __shared__ unsigned long long red[256];
    int b = blockIdx.y, seg = blockIdx.x, t = threadIdx.x;
    for (int i = t; i < SEG_LEN; i += 256) {
        int m = seg * SEG_LEN + i;
        vals[i] = ((unsigned long long)__float_as_uint(g_d2[b * M_BANK + m]) << 32)
                  | (unsigned)m;
    }
    __syncthreads();
    for (int r = 0; r < KNN; r++) {
        unsigned long long mv = vals[t];
        mv = umin64(mv, vals[t + 256]);
        mv = umin64(mv, vals[t + 512]);
        mv = umin64(mv, vals[t + 768]);
        red[t] = mv;
        __syncthreads();
        for (int s = 128; s; s >>= 1) {
            if (t < s) red[t] = umin64(red[t], red[t + s]);
            __syncthreads();
        }
        if (t == 0) {
            unsigned long long sel = red[0];
            g_part[(b * SEGS + seg) * KNN + r] = sel;
            vals[(unsigned)sel - seg * SEG_LEN] = 0xFFFFFFFFFFFFFFFFull;
        }
        __syncthreads();
    }
}

// ---------------- top-9 stage B: merge 288 candidates ----------------
__global__ void topkB_kernel() {
    __shared__ unsigned long long cand[512];
    __shared__ unsigned long long red[512];
    int b = blockIdx.x, t = threadIdx.x;
    cand[t] = (t < SEGS * KNN) ? g_part[b * SEGS * KNN + t]
                               : 0xFFFFFFFFFFFFFFFFull;
    __syncthreads();
    for (int r = 0; r < KNN; r++) {
        red[t] = cand[t];
        __syncthreads();
        for (int s = 256; s; s >>= 1) {
            if (t < s) red[t] = umin64(red[t], red[t + s]);
            __syncthreads();
        }
        unsigned long long sel = red[0];
        if (t == 0) g_support[b * KNN + r] = (int)(sel & 0xFFFFFFFFull);
        if (cand[t] == sel) cand[t] = 0xFFFFFFFFFFFFFFFFull;
        __syncthreads();
    }
}

// ---------------- final: d3, softmax weight, pred_score ----------------
__global__ void final_kernel(const float* __restrict__ E,
                             const float* __restrict__ MB,
                             float* __restrict__ out) {
    int b = blockIdx.x;
    int wid = threadIdx.x >> 5, lane = threadIdx.x & 31;
    __shared__ float d3[KNN];
    int row = g_maxrow[b];
    const float* xf = E + (size_t)row * DIM;
    int sup = g_support[b * KNN + wid];
    const float* pv = MB + (size_t)sup * DIM;
    float s = 0.f;
    for (int k = lane; k < DIM; k += 32) s += xf[k] * pv[k];
    s = warp_sum(s);
    if (!lane)
        d3[wid] = sqrtf(fmaxf(g_xnorm[row] + g_ynorm[sup] - 2.f * s, 0.f));
    __syncthreads();
    if (threadIdx.x == 0) {
        float mx = -FLT_MAX;
        for (int j = 0; j < KNN; j++) mx = fmaxf(mx, d3[j]);
        float den = 0.f, e0 = 0.f;
        for (int j = 0; j < KNN; j++) {
            float e = expf(d3[j] - mx);
            den += e;
            if (j == 0) e0 = e;
        }
        out[N_ROWS + b] = (1.f - e0 / den) * g_score[b];
    }
}

// ---------------- launch ----------------
extern "C" void kernel_launch(void* const* d_in, const int* in_sizes, int n_in,
                              void* d_out, int out_size) {
    (void)n_in; (void)in_sizes; (void)out_size;
    const float* E  = (const float*)d_in[0];
    const float* MB = (const float*)d_in[1];
    float* out = (float*)d_out;

    cudaFuncSetAttribute(gemm_mma_kernel,
                         cudaFuncAttributeMaxDynamicSharedMemorySize, SMEM_BYTES);

    int warps = N_ROWS + M_BANK;
    prep_all_kernel<<<(warps * 32 + 255) / 256, 256>>>(E, MB);

    gemm_mma_kernel<<<dim3(ROW_TILES, GRID_Y), NTHR, SMEM_BYTES>>>();

    batch_reduce_kernel<<<B_SZ, 256>>>();
    write_map_kernel<<<(N_ROWS + 255) / 256, 256>>>(out);
    d2_block_kernel<<<M_BANK / 8, 256>>>(MB);
    topkA_kernel<<<dim3(SEGS, B_SZ), 256>>>();
    topkB_kernel<<<B_SZ, 512>>>();
    final_kernel<<<B_SZ, KNN * 32>>>(E, MB, out);
}

// round 7
// speedup vs baseline: 11.7088x; 1.0028x over previous
#include <cuda_runtime.h>
#include <cuda_fp16.h>
#include <float.h>
#include <stdint.h>

// ---------------- problem constants ----------------
constexpr int N_ROWS  = 6272;
constexpr int M_BANK  = 32768;
constexpr int DIM     = 384;
constexpr int B_SZ    = 8;
constexpr int PATCHES = N_ROWS / B_SZ;
constexpr int KNN     = 9;

// ---------------- GEMM tiling ----------------
constexpr int BM = 128;
constexpr int BN = 256;
constexpr int BK = 64;                 // halves per chunk = 128 bytes/row
constexpr int NCHUNK_K = DIM / BK;     // 6
constexpr int JT_TOTAL = M_BANK / BN;  // 128
constexpr int GRID_Y   = 3;            // 147 CTAs = 1 wave
constexpr int ROW_TILES = N_ROWS / BM; // 49
constexpr int NTHR = 512;              // 16 warps

// SMEM: A-full (6 x 16KB) + 4 B stages x 32KB + ynorm slots / reduce
constexpr int A_CHUNK_BYTES = BM * 128;                   // 16384
constexpr int OFF_B         = NCHUNK_K * A_CHUNK_BYTES;   // 98304
constexpr int B_STAGE_BYTES = BN * 128;                   // 32768
constexpr int YN_OFF        = OFF_B + 4 * B_STAGE_BYTES;  // 229376
// ynorm slots: 2 x 1KB at YN_OFF; reduce buffer (1KB) overlaps slot 0
// (disjoint lifetimes: reduce only after the final epilogue + syncthreads)
constexpr int SMEM_BYTES    = YN_OFF + 2048;              // 231424

// top-k staging
constexpr int SEGS = 32;
constexpr int SEG_LEN = M_BANK / SEGS;  // 1024

// ---------------- device scratch ----------------
__device__ __align__(256) __half g_Eh[N_ROWS * DIM];
__device__ __align__(256) __half g_Bh[M_BANK * DIM];
__device__ float              g_xnorm[N_ROWS];
__device__ float              g_ynorm[M_BANK];
__device__ unsigned long long g_packed[N_ROWS];
__device__ float              g_d2[B_SZ * M_BANK];
__device__ unsigned long long g_part[B_SZ * SEGS * KNN];
__device__ int                g_maxrow[B_SZ];
__device__ float              g_score[B_SZ];
__device__ int                g_nnidx[B_SZ];

// ---------------- helpers ----------------
__device__ __forceinline__ uint32_t smem_u32(const void* p) {
    uint32_t a;
    asm("{ .reg .u64 t; cvta.to.shared.u64 t, %1; cvt.u32.u64 %0, t; }"
        : "=r"(a) : "l"(p));
    return a;
}
__device__ __forceinline__ void cp16(uint32_t dst, const void* src) {
    asm volatile("cp.async.cg.shared.global [%0], [%1], 16;"
                 :: "r"(dst), "l"(src) : "memory");
}
#define CP_COMMIT() asm volatile("cp.async.commit_group;" ::: "memory")
#define CP_WAIT3()  asm volatile("cp.async.wait_group 3;" ::: "memory")

__device__ __forceinline__ uint32_t swz(uint32_t o) { return o ^ ((o >> 3) & 0x70); }

__device__ __forceinline__ void ldmA(uint32_t base, int r_base, int kb,
                                     int lane, uint32_t* f) {
    int q = lane >> 3;
    int r = r_base + (q & 1) * 8 + (lane & 7);
    int kk = kb + (q >> 1) * 16;
    uint32_t a = base + swz((uint32_t)(r * 128 + kk));
    asm volatile("ldmatrix.sync.aligned.m8n8.x4.shared.b16 {%0,%1,%2,%3}, [%4];"
                 : "=r"(f[0]), "=r"(f[1]), "=r"(f[2]), "=r"(f[3]) : "r"(a));
}
__device__ __forceinline__ void ldmB4(uint32_t base, int n_base, int kb,
                                      int lane, uint32_t* f) {
    int q = lane >> 3;
    int n = n_base + (q >> 1) * 8 + (lane & 7);
    int kk = kb + (q & 1) * 16;
    uint32_t a = base + swz((uint32_t)(n * 128 + kk));
    asm volatile("ldmatrix.sync.aligned.m8n8.x4.shared.b16 {%0,%1,%2,%3}, [%4];"
                 : "=r"(f[0]), "=r"(f[1]), "=r"(f[2]), "=r"(f[3]) : "r"(a));
}
__device__ __forceinline__ void mma_f16(float* c, const uint32_t* a,
                                        const uint32_t* b) {
    asm volatile(
        "mma.sync.aligned.m16n8k16.row.col.f32.f16.f16.f32 "
        "{%0,%1,%2,%3},{%4,%5,%6,%7},{%8,%9},{%0,%1,%2,%3};"
        : "+f"(c[0]), "+f"(c[1]), "+f"(c[2]), "+f"(c[3])
        : "r"(a[0]), "r"(a[1]), "r"(a[2]), "r"(a[3]), "r"(b[0]), "r"(b[1]));
}
__device__ __forceinline__ float warp_sum(float s) {
#pragma unroll
    for (int o = 16; o; o >>= 1) s += __shfl_xor_sync(0xFFFFFFFFu, s, o);
    return s;
}
__device__ __forceinline__ unsigned long long umin64(unsigned long long a,
                                                     unsigned long long b) {
    return a < b ? a : b;
}
__device__ __forceinline__ void fold_min(unsigned long long& best, float xn,
                                         float yn, float dot, int col) {
    float d = fmaxf(fmaf(-2.f, dot, xn + yn), 0.f);
    unsigned long long p =
        ((unsigned long long)__float_as_uint(d) << 32) | (unsigned)col;
    best = umin64(best, p);
}

// ---------------- fused prep: fp16 convert + norms + packed init ----------------
__global__ void prep_all_kernel(const float* __restrict__ E,
                                const float* __restrict__ MB) {
    int warp = (blockIdx.x * blockDim.x + threadIdx.x) >> 5;
    int lane = threadIdx.x & 31;
    if (warp >= N_ROWS + M_BANK) return;
    bool isE = warp < N_ROWS;
    int row = isE ? warp : warp - N_ROWS;
    const float* src = isE ? E : MB;
    __half* dsth = isE ? g_Eh : g_Bh;
    const float4* p =
        reinterpret_cast<const float4*>(src + (size_t)row * DIM + lane * 12);
    __half2* dst =
        reinterpret_cast<__half2*>(dsth + (size_t)row * DIM + lane * 12);
    float s = 0.f;
#pragma unroll
    for (int v = 0; v < 3; v++) {
        float4 f = p[v];
        s += f.x * f.x + f.y * f.y + f.z * f.z + f.w * f.w;
        dst[v * 2]     = __floats2half2_rn(f.x, f.y);
        dst[v * 2 + 1] = __floats2half2_rn(f.z, f.w);
    }
    s = warp_sum(s);
    if (!lane) {
        if (isE) { g_xnorm[row] = s; g_packed[row] = 0xFFFFFFFFFFFFFFFFull; }
        else     g_ynorm[row] = s;
    }
}

// ---------------- B chunk (+ per-tile ynorm) loader ----------------
__device__ __forceinline__ void load_B(uint32_t sb, int c, int jt0, int t) {
    uint32_t sbase = sb + OFF_B + (c & 3) * B_STAGE_BYTES;
    int tl  = c / NCHUNK_K;
    int j0  = (jt0 + tl) * BN;
    int kof = (c % NCHUNK_K) * BK;
#pragma unroll 4
    for (int i = t; i < BN * 8; i += NTHR) {
        int r = i >> 3, g = i & 7;
        uint32_t d = swz((uint32_t)(r * 128 + g * 16));
        cp16(sbase + d, g_Bh + (size_t)(j0 + r) * DIM + kof + g * 8);
    }
    // first chunk of a j-tile: also prefetch its 1KB ynorm slice
    if ((c % NCHUNK_K) == 0 && t < 64)
        cp16(sb + YN_OFF + (tl & 1) * 1024 + t * 16, g_ynorm + j0 + t * 4);
}

// ---------------- main GEMM + fused min/argmin ----------------
__global__ __launch_bounds__(NTHR, 1) void gemm_mma_kernel() {
    extern __shared__ __align__(1024) char smem[];
    uint32_t sb = smem_u32(smem);
    const float* ynbuf = (const float*)(smem + YN_OFF);
    unsigned long long* red = (unsigned long long*)(smem + YN_OFF);

    const int t = threadIdx.x;
    const int w = t >> 5, lane = t & 31;
    const int gid = lane >> 2, tig = lane & 3;
    const int wm = w & 1, wn = w >> 1;     // warp tile: rows wm*64, cols wn*32
    const int row0 = blockIdx.x * BM;
    const int jt0 = blockIdx.y * 43;
    const int jt1 = (jt0 + 43 < JT_TOTAL) ? jt0 + 43 : JT_TOTAL;
    const int TOT = (jt1 - jt0) * NCHUNK_K;

    float xnA[4], xnB[4];
#pragma unroll
    for (int i = 0; i < 4; i++) {
        xnA[i] = g_xnorm[row0 + wm * 64 + i * 16 + gid];
        xnB[i] = g_xnorm[row0 + wm * 64 + i * 16 + gid + 8];
    }

    unsigned long long bestA[4], bestB[4];
#pragma unroll
    for (int i = 0; i < 4; i++) bestA[i] = bestB[i] = 0xFFFFFFFFFFFFFFFFull;

    // prologue: A full-K resident (group 0)
#pragma unroll
    for (int ck = 0; ck < NCHUNK_K; ck++) {
        for (int i = t; i < BM * 8; i += NTHR) {
            int r = i >> 3, g = i & 7;
            uint32_t d = swz((uint32_t)(r * 128 + g * 16));
            cp16(sb + ck * A_CHUNK_BYTES + d,
                 g_Eh + (size_t)(row0 + r) * DIM + ck * BK + g * 8);
        }
    }
    CP_COMMIT();
    for (int p = 0; p < 3; p++) { load_B(sb, p, jt0, t); CP_COMMIT(); }

    float acc[4][4][4];
#pragma unroll
    for (int i = 0; i < 4; i++)
#pragma unroll
        for (int j = 0; j < 4; j++)
#pragma unroll
            for (int q = 0; q < 4; q++) acc[i][j][q] = 0.f;

    for (int c = 0; c < TOT; c++) {
        CP_WAIT3();            // chunk c (and A, and ynorm of its tile) resident
        __syncthreads();
        if (c + 3 < TOT) load_B(sb, c + 3, jt0, t);
        CP_COMMIT();

        const int ck = c % NCHUNK_K;
        const uint32_t sA = sb + ck * A_CHUNK_BYTES;
        const uint32_t sB = sb + OFF_B + (c & 3) * B_STAGE_BYTES;

#pragma unroll
        for (int kk = 0; kk < BK / 16; kk++) {
            const int kb = kk * 32;   // bytes
            uint32_t Af[4][4], Bf[4][2];
#pragma unroll
            for (int jj = 0; jj < 2; jj++) {
                uint32_t f[4];
                ldmB4(sB, wn * 32 + jj * 16, kb, lane, f);
                Bf[2 * jj][0] = f[0]; Bf[2 * jj][1] = f[1];
                Bf[2 * jj + 1][0] = f[2]; Bf[2 * jj + 1][1] = f[3];
            }
#pragma unroll
            for (int i = 0; i < 4; i++)
                ldmA(sA, wm * 64 + i * 16, kb, lane, Af[i]);
#pragma unroll
            for (int i = 0; i < 4; i++)
#pragma unroll
                for (int j = 0; j < 4; j++)
                    mma_f16(acc[i][j], Af[i], Bf[j]);
        }

        if (ck == NCHUNK_K - 1) {
            const int tl = c / NCHUNK_K;
            const int j0 = (jt0 + tl) * BN;
            const float* yn = ynbuf + (tl & 1) * 256;
#pragma unroll
            for (int i = 0; i < 4; i++)
#pragma unroll
                for (int j = 0; j < 4; j++) {
                    int cl = wn * 32 + j * 8 + tig * 2;
                    float yn0 = yn[cl], yn1 = yn[cl + 1];
                    int col = j0 + cl;
                    fold_min(bestA[i], xnA[i], yn0, acc[i][j][0], col);
                    fold_min(bestA[i], xnA[i], yn1, acc[i][j][1], col + 1);
                    fold_min(bestB[i], xnB[i], yn0, acc[i][j][2], col);
                    fold_min(bestB[i], xnB[i], yn1, acc[i][j][3], col + 1);
                    acc[i][j][0] = acc[i][j][1] = acc[i][j][2] = acc[i][j][3] = 0.f;
                }
        }
    }

    // reduce across tig lanes (same row)
#pragma unroll
    for (int i = 0; i < 4; i++) {
#pragma unroll
        for (int off = 1; off <= 2; off <<= 1) {
            bestA[i] = umin64(bestA[i], __shfl_xor_sync(0xFFFFFFFFu, bestA[i], off));
            bestB[i] = umin64(bestB[i], __shfl_xor_sync(0xFFFFFFFFu, bestB[i], off));
        }
    }

    __syncthreads();   // ynorm slots dead; reuse region as reduce buffer
    if (t < BM) red[t] = 0xFFFFFFFFFFFFFFFFull;
    __syncthreads();
    if (tig == 0) {
#pragma unroll
        for (int i = 0; i < 4; i++) {
            atomicMin(&red[wm * 64 + i * 16 + gid], bestA[i]);
            atomicMin(&red[wm * 64 + i * 16 + gid + 8], bestB[i]);
        }
    }
    __syncthreads();
    if (t < BM) atomicMin(&g_packed[row0 + t], red[t]);
}

// ---------------- tail: batch argmax + patch map write (fused) ----------------
__global__ void batch_map_kernel(float* __restrict__ out) {
    int b = blockIdx.x, t = threadIdx.x;
    __shared__ float sv[256];
    __shared__ int   si[256];
    float bv = -1.f; int bi = PATCHES;
    for (int p = t; p < PATCHES; p += 256) {
        unsigned long long pk = g_packed[b * PATCHES + p];
        float d = __uint_as_float((unsigned)(pk >> 32));
        out[b * PATCHES + p] = sqrtf(d);
        if (d > bv || (d == bv && p < bi)) { bv = d; bi = p; }
    }
    sv[t] = bv; si[t] = bi;
    __syncthreads();
    for (int s = 128; s; s >>= 1) {
        if (t < s) {
            if (sv[t + s] > sv[t] || (sv[t + s] == sv[t] && si[t + s] < si[t])) {
                sv[t] = sv[t + s]; si[t] = si[t + s];
            }
        }
        __syncthreads();
    }
    if (t == 0) {
        int row = b * PATCHES + si[0];
        unsigned long long pk = g_packed[row];
        g_maxrow[b] = row;
        g_score[b]  = sqrtf(__uint_as_float((unsigned)(pk >> 32)));
        g_nnidx[b]  = (int)(pk & 0xFFFFFFFFull);
    }
}

// ---------------- d2: bank read once, all 8 batches per pass ----------------
__global__ void d2_block_kernel(const float* __restrict__ MB) {
    __shared__ float4 nn4[B_SZ][DIM / 4];   // 12 KB
    __shared__ float  nyn[B_SZ];
    int t = threadIdx.x, wid = t >> 5, lane = t & 31;
    for (int i = t; i < B_SZ * (DIM / 4); i += 256) {
        int b = i / (DIM / 4), v = i % (DIM / 4);
        nn4[b][v] = reinterpret_cast<const float4*>(
            MB + (size_t)g_nnidx[b] * DIM)[v];
    }
    if (t < B_SZ) nyn[t] = g_ynorm[g_nnidx[t]];
    __syncthreads();

    int m = blockIdx.x * 8 + wid;
    const float4* pm4 = reinterpret_cast<const float4*>(MB + (size_t)m * DIM);
    float s[B_SZ];
#pragma unroll
    for (int b = 0; b < B_SZ; b++) s[b] = 0.f;
#pragma unroll
    for (int v = 0; v < 3; v++) {
        float4 f = pm4[lane + v * 32];
#pragma unroll
        for (int b = 0; b < B_SZ; b++) {
            float4 g = nn4[b][lane + v * 32];
            s[b] += f.x * g.x + f.y * g.y + f.z * g.z + f.w * g.w;
        }
    }
#pragma unroll
    for (int b = 0; b < B_SZ; b++) s[b] = warp_sum(s[b]);
    if (lane == 0) {
        float ym = g_ynorm[m];
#pragma unroll
        for (int b = 0; b < B_SZ; b++)
            g_d2[b * M_BANK + m] = fmaxf(nyn[b] + ym - 2.f * s[b], 0.f);
    }
}

// ---------------- top-9 stage A: per-segment selection ----------------
__global__ void topkA_kernel() {
    __shared__ unsigned long long vals[SEG_LEN];
    __shared__ unsigned long long red[256];
    int b = blockIdx.y, seg = blockIdx.x, t = threadIdx.x;
    for (int i = t; i < SEG_LEN; i += 256) {
        int m = seg * SEG_LEN + i;
        vals[i] = ((unsigned long long)__float_as_uint(g_d2[b * M_BANK + m]) << 32)
                  | (unsigned)m;
    }
    __syncthreads();
    for (int r = 0; r < KNN; r++) {
        unsigned long long mv = vals[t];
        mv = umin64(mv, vals[t + 256]);
        mv = umin64(mv, vals[t + 512]);
        mv = umin64(mv, vals[t + 768]);
        red[t] = mv;
        __syncthreads();
        for (int s = 128; s; s >>= 1) {
            if (t < s) red[t] = umin64(red[t], red[t + s]);
            __syncthreads();
        }
        if (t == 0) {
            unsigned long long sel = red[0];
            g_part[(b * SEGS + seg) * KNN + r] = sel;
            vals[(unsigned)sel - seg * SEG_LEN] = 0xFFFFFFFFFFFFFFFFull;
        }
        __syncthreads();
    }
}

// ---------------- top-9 merge + final score (fused) ----------------
__global__ void topk_final_kernel(const float* __restrict__ E,
                                  const float* __restrict__ MB,
                                  float* __restrict__ out) {
    __shared__ unsigned long long cand[512];
    __shared__ unsigned long long red[512];
    __shared__ int   sup[KNN];
    __shared__ float d3[KNN];
    int b = blockIdx.x, t = threadIdx.x;
    cand[t] = (t < SEGS * KNN) ? g_part[b * SEGS * KNN + t]
                               : 0xFFFFFFFFFFFFFFFFull;
    __syncthreads();
    for (int r = 0; r < KNN; r++) {
        red[t] = cand[t];
        __syncthreads();
        for (int s = 256; s; s >>= 1) {
            if (t < s) red[t] = umin64(red[t], red[t + s]);
            __syncthreads();
        }
        unsigned long long sel = red[0];
        if (t == 0) sup[r] = (int)(sel & 0xFFFFFFFFull);
        if (cand[t] == sel) cand[t] = 0xFFFFFFFFFFFFFFFFull;
        __syncthreads();
    }

    // d3 + softmax weight, 9 warps do the dot products
    int wid = t >> 5, lane = t & 31;
    int row = g_maxrow[b];
    if (wid < KNN) {
        const float* xf = E + (size_t)row * DIM;
        int sp = sup[wid];
        const float* pv = MB + (size_t)sp * DIM;
        float s = 0.f;
        for (int k = lane; k < DIM; k += 32) s += xf[k] * pv[k];
        s = warp_sum(s);
        if (!lane)
            d3[wid] = sqrtf(fmaxf(g_xnorm[row] + g_ynorm[sp] - 2.f * s, 0.f));
    }
    __syncthreads();
    if (t == 0) {
        float mx = -FLT_MAX;
        for (int j = 0; j < KNN; j++) mx = fmaxf(mx, d3[j]);
        float den = 0.f, e0 = 0.f;
        for (int j = 0; j < KNN; j++) {
            float e = expf(d3[j] - mx);
            den += e;
            if (j == 0) e0 = e;
        }
        out[N_ROWS + b] = (1.f - e0 / den) * g_score[b];
    }
}

// ---------------- launch ----------------
extern "C" void kernel_launch(void* const* d_in, const int* in_sizes, int n_in,
                              void* d_out, int out_size) {
    (void)n_in; (void)in_sizes; (void)out_size;
    const float* E  = (const float*)d_in[0];
    const float* MB = (const float*)d_in[1];
    float* out = (float*)d_out;

    cudaFuncSetAttribute(gemm_mma_kernel,
                         cudaFuncAttributeMaxDynamicSharedMemorySize, SMEM_BYTES);

    int warps = N_ROWS + M_BANK;
    prep_all_kernel<<<(warps * 32 + 255) / 256, 256>>>(E, MB);

    gemm_mma_kernel<<<dim3(ROW_TILES, GRID_Y), NTHR, SMEM_BYTES>>>();

    batch_map_kernel<<<B_SZ, 256>>>(out);
    d2_block_kernel<<<M_BANK / 8, 256>>>(MB);
    topkA_kernel<<<dim3(SEGS, B_SZ), 256>>>();
    topk_final_kernel<<<B_SZ, 512>>>(E, MB, out);
}

// round 8
// speedup vs baseline: 12.0044x; 1.0252x over previous
#include <cuda_runtime.h>
#include <cuda_fp16.h>
#include <float.h>
#include <stdint.h>

// ---------------- problem constants ----------------
constexpr int N_ROWS  = 6272;
constexpr int M_BANK  = 32768;
constexpr int DIM     = 384;
constexpr int B_SZ    = 8;
constexpr int PATCHES = N_ROWS / B_SZ;
constexpr int KNN     = 9;

// ---------------- GEMM tiling ----------------
constexpr int BM = 128;
constexpr int BN = 256;
constexpr int BK = 64;                 // halves per chunk = 128 bytes/row
constexpr int NCHUNK_K = DIM / BK;     // 6
constexpr int JT_TOTAL = M_BANK / BN;  // 128
constexpr int GRID_Y   = 3;            // 147 CTAs = 1 wave
constexpr int ROW_TILES = N_ROWS / BM; // 49
constexpr int NTHR = 256;              // 8 warps (regs: 255 budget, no spill)

// SMEM: A-full (6 x 16KB) + 4 B stages x 32KB + ynorm slots / reduce
constexpr int A_CHUNK_BYTES = BM * 128;                   // 16384
constexpr int OFF_B         = NCHUNK_K * A_CHUNK_BYTES;   // 98304
constexpr int B_STAGE_BYTES = BN * 128;                   // 32768
constexpr int YN_OFF        = OFF_B + 4 * B_STAGE_BYTES;  // 229376
constexpr int SMEM_BYTES    = YN_OFF + 2048;              // 231424

// top-k staging
constexpr int SEGS = 32;
constexpr int SEG_LEN = M_BANK / SEGS;  // 1024

// ---------------- device scratch ----------------
__device__ __align__(256) __half g_Eh[N_ROWS * DIM];
__device__ __align__(256) __half g_Bh[M_BANK * DIM];
__device__ float              g_xnorm[N_ROWS];
__device__ float              g_ynorm[M_BANK];
__device__ unsigned long long g_packed[N_ROWS];
__device__ float              g_d2[B_SZ * M_BANK];
__device__ unsigned long long g_part[B_SZ * SEGS * KNN];
__device__ int                g_maxrow[B_SZ];
__device__ float              g_score[B_SZ];
__device__ int                g_nnidx[B_SZ];

// ---------------- helpers ----------------
__device__ __forceinline__ uint32_t smem_u32(const void* p) {
    uint32_t a;
    asm("{ .reg .u64 t; cvta.to.shared.u64 t, %1; cvt.u32.u64 %0, t; }"
        : "=r"(a) : "l"(p));
    return a;
}
__device__ __forceinline__ void cp16(uint32_t dst, const void* src) {
    asm volatile("cp.async.cg.shared.global [%0], [%1], 16;"
                 :: "r"(dst), "l"(src) : "memory");
}
#define CP_COMMIT() asm volatile("cp.async.commit_group;" ::: "memory")
#define CP_WAIT3()  asm volatile("cp.async.wait_group 3;" ::: "memory")

__device__ __forceinline__ uint32_t swz(uint32_t o) { return o ^ ((o >> 3) & 0x70); }

__device__ __forceinline__ void ldmA(uint32_t base, int r_base, int kb,
                                     int lane, uint32_t* f) {
    int q = lane >> 3;
    int r = r_base + (q & 1) * 8 + (lane & 7);
    int kk = kb + (q >> 1) * 16;
    uint32_t a = base + swz((uint32_t)(r * 128 + kk));
    asm volatile("ldmatrix.sync.aligned.m8n8.x4.shared.b16 {%0,%1,%2,%3}, [%4];"
                 : "=r"(f[0]), "=r"(f[1]), "=r"(f[2]), "=r"(f[3]) : "r"(a));
}
__device__ __forceinline__ void ldmB4(uint32_t base, int n_base, int kb,
                                      int lane, uint32_t* f) {
    int q = lane >> 3;
    int n = n_base + (q >> 1) * 8 + (lane & 7);
    int kk = kb + (q & 1) * 16;
    uint32_t a = base + swz((uint32_t)(n * 128 + kk));
    asm volatile("ldmatrix.sync.aligned.m8n8.x4.shared.b16 {%0,%1,%2,%3}, [%4];"
                 : "=r"(f[0]), "=r"(f[1]), "=r"(f[2]), "=r"(f[3]) : "r"(a));
}
__device__ __forceinline__ void mma_f16(float* c, const uint32_t* a,
                                        const uint32_t* b) {
    asm volatile(
        "mma.sync.aligned.m16n8k16.row.col.f32.f16.f16.f32 "
        "{%0,%1,%2,%3},{%4,%5,%6,%7},{%8,%9},{%0,%1,%2,%3};"
        : "+f"(c[0]), "+f"(c[1]), "+f"(c[2]), "+f"(c[3])
        : "r"(a[0]), "r"(a[1]), "r"(a[2]), "r"(a[3]), "r"(b[0]), "r"(b[1]));
}
__device__ __forceinline__ float warp_sum(float s) {
#pragma unroll
    for (int o = 16; o; o >>= 1) s += __shfl_xor_sync(0xFFFFFFFFu, s, o);
    return s;
}
__device__ __forceinline__ unsigned long long umin64(unsigned long long a,
                                                     unsigned long long b) {
    return a < b ? a : b;
}
__device__ __forceinline__ void fold_min(unsigned long long& best, float xn,
                                         float yn, float dot, int col) {
    float d = fmaxf(fmaf(-2.f, dot, xn + yn), 0.f);
    unsigned long long p =
        ((unsigned long long)__float_as_uint(d) << 32) | (unsigned)col;
    best = umin64(best, p);
}

// ---------------- fused prep: fp16 convert + norms + packed init ----------------
__global__ void prep_all_kernel(const float* __restrict__ E,
                                const float* __restrict__ MB) {
    int warp = (blockIdx.x * blockDim.x + threadIdx.x) >> 5;
    int lane = threadIdx.x & 31;
    if (warp >= N_ROWS + M_BANK) return;
    bool isE = warp < N_ROWS;
    int row = isE ? warp : warp - N_ROWS;
    const float* src = isE ? E : MB;
    __half* dsth = isE ? g_Eh : g_Bh;
    const float4* p =
        reinterpret_cast<const float4*>(src + (size_t)row * DIM + lane * 12);
    __half2* dst =
        reinterpret_cast<__half2*>(dsth + (size_t)row * DIM + lane * 12);
    float s = 0.f;
#pragma unroll
    for (int v = 0; v < 3; v++) {
        float4 f = p[v];
        s += f.x * f.x + f.y * f.y + f.z * f.z + f.w * f.w;
        dst[v * 2]     = __floats2half2_rn(f.x, f.y);
        dst[v * 2 + 1] = __floats2half2_rn(f.z, f.w);
    }
    s = warp_sum(s);
    if (!lane) {
        if (isE) { g_xnorm[row] = s; g_packed[row] = 0xFFFFFFFFFFFFFFFFull; }
        else     g_ynorm[row] = s;
    }
}

// ---------------- B chunk (+ per-tile ynorm) loader ----------------
__device__ __forceinline__ void load_B(uint32_t sb, int c, int jt0, int t) {
    uint32_t sbase = sb + OFF_B + (c & 3) * B_STAGE_BYTES;
    int tl  = c / NCHUNK_K;
    int j0  = (jt0 + tl) * BN;
    int kof = (c % NCHUNK_K) * BK;
#pragma unroll 8
    for (int i = t; i < BN * 8; i += NTHR) {
        int r = i >> 3, g = i & 7;
        uint32_t d = swz((uint32_t)(r * 128 + g * 16));
        cp16(sbase + d, g_Bh + (size_t)(j0 + r) * DIM + kof + g * 8);
    }
    if ((c % NCHUNK_K) == 0 && t < 64)
        cp16(sb + YN_OFF + (tl & 1) * 1024 + t * 16, g_ynorm + j0 + t * 4);
}

// ---------------- main GEMM + fused min/argmin ----------------
__global__ __launch_bounds__(NTHR, 1) void gemm_mma_kernel() {
    extern __shared__ __align__(1024) char smem[];
    uint32_t sb = smem_u32(smem);
    const float* ynbuf = (const float*)(smem + YN_OFF);
    unsigned long long* red = (unsigned long long*)(smem + YN_OFF);

    const int t = threadIdx.x;
    const int w = t >> 5, lane = t & 31;
    const int gid = lane >> 2, tig = lane & 3;
    const int wm = w & 1, wn = w >> 1;     // warp tile: rows wm*64, cols wn*64
    const int row0 = blockIdx.x * BM;
    const int jt0 = blockIdx.y * 43;
    const int jt1 = (jt0 + 43 < JT_TOTAL) ? jt0 + 43 : JT_TOTAL;
    const int TOT = (jt1 - jt0) * NCHUNK_K;

    float xnA[4], xnB[4];
#pragma unroll
    for (int i = 0; i < 4; i++) {
        xnA[i] = g_xnorm[row0 + wm * 64 + i * 16 + gid];
        xnB[i] = g_xnorm[row0 + wm * 64 + i * 16 + gid + 8];
    }

    unsigned long long bestA[4], bestB[4];
#pragma unroll
    for (int i = 0; i < 4; i++) bestA[i] = bestB[i] = 0xFFFFFFFFFFFFFFFFull;

    // prologue: A full-K resident (group 0)
#pragma unroll
    for (int ck = 0; ck < NCHUNK_K; ck++) {
        for (int i = t; i < BM * 8; i += NTHR) {
            int r = i >> 3, g = i & 7;
            uint32_t d = swz((uint32_t)(r * 128 + g * 16));
            cp16(sb + ck * A_CHUNK_BYTES + d,
                 g_Eh + (size_t)(row0 + r) * DIM + ck * BK + g * 8);
        }
    }
    CP_COMMIT();
    for (int p = 0; p < 3; p++) { load_B(sb, p, jt0, t); CP_COMMIT(); }

    float acc[4][8][4];
#pragma unroll
    for (int i = 0; i < 4; i++)
#pragma unroll
        for (int j = 0; j < 8; j++)
#pragma unroll
            for (int q = 0; q < 4; q++) acc[i][j][q] = 0.f;

    for (int c = 0; c < TOT; c++) {
        CP_WAIT3();
        __syncthreads();
        if (c + 3 < TOT) load_B(sb, c + 3, jt0, t);
        CP_COMMIT();

        const int ck = c % NCHUNK_K;
        const uint32_t sA = sb + ck * A_CHUNK_BYTES;
        const uint32_t sB = sb + OFF_B + (c & 3) * B_STAGE_BYTES;

#pragma unroll
        for (int kk = 0; kk < BK / 16; kk++) {
            const int kb = kk * 32;   // bytes
            uint32_t Af[4][4], Bf[8][2];
#pragma unroll
            for (int jj = 0; jj < 4; jj++) {
                uint32_t f[4];
                ldmB4(sB, wn * 64 + jj * 16, kb, lane, f);
                Bf[2 * jj][0] = f[0]; Bf[2 * jj][1] = f[1];
                Bf[2 * jj + 1][0] = f[2]; Bf[2 * jj + 1][1] = f[3];
            }
#pragma unroll
            for (int i = 0; i < 4; i++)
                ldmA(sA, wm * 64 + i * 16, kb, lane, Af[i]);
#pragma unroll
            for (int i = 0; i < 4; i++)
#pragma unroll
                for (int j = 0; j < 8; j++)
                    mma_f16(acc[i][j], Af[i], Bf[j]);
        }

        if (ck == NCHUNK_K - 1) {
            const int tl = c / NCHUNK_K;
            const int j0 = (jt0 + tl) * BN;
            const float* yn = ynbuf + (tl & 1) * 256;
#pragma unroll
            for (int i = 0; i < 4; i++)
#pragma unroll
                for (int j = 0; j < 8; j++) {
                    int cl = wn * 64 + j * 8 + tig * 2;
                    float yn0 = yn[cl], yn1 = yn[cl + 1];
                    int col = j0 + cl;
                    fold_min(bestA[i], xnA[i], yn0, acc[i][j][0], col);
                    fold_min(bestA[i], xnA[i], yn1, acc[i][j][1], col + 1);
                    fold_min(bestB[i], xnB[i], yn0, acc[i][j][2], col);
                    fold_min(bestB[i], xnB[i], yn1, acc[i][j][3], col + 1);
                    acc[i][j][0] = acc[i][j][1] = acc[i][j][2] = acc[i][j][3] = 0.f;
                }
        }
    }

    // reduce across tig lanes (same row)
#pragma unroll
    for (int i = 0; i < 4; i++) {
#pragma unroll
        for (int off = 1; off <= 2; off <<= 1) {
            bestA[i] = umin64(bestA[i], __shfl_xor_sync(0xFFFFFFFFu, bestA[i], off));
            bestB[i] = umin64(bestB[i], __shfl_xor_sync(0xFFFFFFFFu, bestB[i], off));
        }
    }

    __syncthreads();   // ynorm slots dead; reuse region as reduce buffer
    if (t < BM) red[t] = 0xFFFFFFFFFFFFFFFFull;
    __syncthreads();
    if (tig == 0) {
#pragma unroll
        for (int i = 0; i < 4; i++) {
            atomicMin(&red[wm * 64 + i * 16 + gid], bestA[i]);
            atomicMin(&red[wm * 64 + i * 16 + gid + 8], bestB[i]);
        }
    }
    __syncthreads();
    if (t < BM) atomicMin(&g_packed[row0 + t], red[t]);
}

// ---------------- tail: batch argmax + patch map write (fused) ----------------
__global__ void batch_map_kernel(float* __restrict__ out) {
    int b = blockIdx.x, t = threadIdx.x;
    __shared__ float sv[256];
    __shared__ int   si[256];
    float bv = -1.f; int bi = PATCHES;
    for (int p = t; p < PATCHES; p += 256) {
        unsigned long long pk = g_packed[b * PATCHES + p];
        float d = __uint_as_float((unsigned)(pk >> 32));
        out[b * PATCHES + p] = sqrtf(d);
        if (d > bv || (d == bv && p < bi)) { bv = d; bi = p; }
    }
    sv[t] = bv; si[t] = bi;
    __syncthreads();
    for (int s = 128; s; s >>= 1) {
        if (t < s) {
            if (sv[t + s] > sv[t] || (sv[t + s] == sv[t] && si[t + s] < si[t])) {
                sv[t] = sv[t + s]; si[t] = si[t + s];
            }
        }
        __syncthreads();
    }
    if (t == 0) {
        int row = b * PATCHES + si[0];
        unsigned long long pk = g_packed[row];
        g_maxrow[b] = row;
        g_score[b]  = sqrtf(__uint_as_float((unsigned)(pk >> 32)));
        g_nnidx[b]  = (int)(pk & 0xFFFFFFFFull);
    }
}

// ---------------- d2: bank read once, all 8 batches per pass ----------------
__global__ void d2_block_kernel(const float* __restrict__ MB) {
    __shared__ float4 nn4[B_SZ][DIM / 4];   // 12 KB
    __shared__ float  nyn[B_SZ];
    int t = threadIdx.x, wid = t >> 5, lane = t & 31;
    for (int i = t; i < B_SZ * (DIM / 4); i += 256) {
        int b = i / (DIM / 4), v = i % (DIM / 4);
        nn4[b][v] = reinterpret_cast<const float4*>(
            MB + (size_t)g_nnidx[b] * DIM)[v];
    }
    if (t < B_SZ) nyn[t] = g_ynorm[g_nnidx[t]];
    __syncthreads();

    int m = blockIdx.x * 8 + wid;
    const float4* pm4 = reinterpret_cast<const float4*>(MB + (size_t)m * DIM);
    float s[B_SZ];
#pragma unroll
    for (int b = 0; b < B_SZ; b++) s[b] = 0.f;
#pragma unroll
    for (int v = 0; v < 3; v++) {
        float4 f = pm4[lane + v * 32];
#pragma unroll
        for (int b = 0; b < B_SZ; b++) {
            float4 g = nn4[b][lane + v * 32];
            s[b] += f.x * g.x + f.y * g.y + f.z * g.z + f.w * g.w;
        }
    }
#pragma unroll
    for (int b = 0; b < B_SZ; b++) s[b] = warp_sum(s[b]);
    if (lane == 0) {
        float ym = g_ynorm[m];
#pragma unroll
        for (int b = 0; b < B_SZ; b++)
            g_d2[b * M_BANK + m] = fmaxf(nyn[b] + ym - 2.f * s[b], 0.f);
    }
}

// ---------------- top-9 stage A: per-segment selection ----------------
__global__ void topkA_kernel() {
    __shared__ unsigned long long vals[SEG_LEN];
    __shared__ unsigned long long red[256];
    int b = blockIdx.y, seg = blockIdx.x, t = threadIdx.x;
    for (int i = t; i < SEG_LEN; i += 256) {
        int m = seg * SEG_LEN + i;
        vals[i] = ((unsigned long long)__float_as_uint(g_d2[b * M_BANK + m]) << 32)
                  | (unsigned)m;
    }
    __syncthreads();
    for (int r = 0; r < KNN; r++) {
        unsigned long long mv = vals[t];
        mv = umin64(mv, vals[t + 256]);
        mv = umin64(mv, vals[t + 512]);
        mv = umin64(mv, vals[t + 768]);
        red[t] = mv;
        __syncthreads();
        for (int s = 128; s; s >>= 1) {
            if (t < s) red[t] = umin64(red[t], red[t + s]);
            __syncthreads();
        }
        if (t == 0) {
            unsigned long long sel = red[0];
            g_part[(b * SEGS + seg) * KNN + r] = sel;
            vals[(unsigned)sel - seg * SEG_LEN] = 0xFFFFFFFFFFFFFFFFull;
        }
        __syncthreads();
    }
}

// ---------------- top-9 merge + final score (fused) ----------------
__global__ void topk_final_kernel(const float* __restrict__ E,
                                  const float* __restrict__ MB,
                                  float* __restrict__ out) {
    __shared__ unsigned long long cand[512];
    __shared__ unsigned long long red[512];
    __shared__ int   sup[KNN];
    __shared__ float d3[KNN];
    int b = blockIdx.x, t = threadIdx.x;
    cand[t] = (t < SEGS * KNN) ? g_part[b * SEGS * KNN + t]
                               : 0xFFFFFFFFFFFFFFFFull;
    __syncthreads();
    for (int r = 0; r < KNN; r++) {
        red[t] = cand[t];
        __syncthreads();
        for (int s = 256; s; s >>= 1) {
            if (t < s) red[t] = umin64(red[t], red[t + s]);
            __syncthreads();
        }
        unsigned long long sel = red[0];
        if (t == 0) sup[r] = (int)(sel & 0xFFFFFFFFull);
        if (cand[t] == sel) cand[t] = 0xFFFFFFFFFFFFFFFFull;
        __syncthreads();
    }

    int wid = t >> 5, lane = t & 31;
    int row = g_maxrow[b];
    if (wid < KNN) {
        const float* xf = E + (size_t)row * DIM;
        int sp = sup[wid];
        const float* pv = MB + (size_t)sp * DIM;
        float s = 0.f;
        for (int k = lane; k < DIM; k += 32) s += xf[k] * pv[k];
        s = warp_sum(s);
        if (!lane)
            d3[wid] = sqrtf(fmaxf(g_xnorm[row] + g_ynorm[sp] - 2.f * s, 0.f));
    }
    __syncthreads();
    if (t == 0) {
        float mx = -FLT_MAX;
        for (int j = 0; j < KNN; j++) mx = fmaxf(mx, d3[j]);
        float den = 0.f, e0 = 0.f;
        for (int j = 0; j < KNN; j++) {
            float e = expf(d3[j] - mx);
            den += e;
            if (j == 0) e0 = e;
        }
        out[N_ROWS + b] = (1.f - e0 / den) * g_score[b];
    }
}

// ---------------- launch ----------------
extern "C" void kernel_launch(void* const* d_in, const int* in_sizes, int n_in,
                              void* d_out, int out_size) {
    (void)n_in; (void)in_sizes; (void)out_size;
    const float* E  = (const float*)d_in[0];
    const float* MB = (const float*)d_in[1];
    float* out = (float*)d_out;

    cudaFuncSetAttribute(gemm_mma_kernel,
                         cudaFuncAttributeMaxDynamicSharedMemorySize, SMEM_BYTES);

    int warps = N_ROWS + M_BANK;
    prep_all_kernel<<<(warps * 32 + 255) / 256, 256>>>(E, MB);

    gemm_mma_kernel<<<dim3(ROW_TILES, GRID_Y), NTHR, SMEM_BYTES>>>();

    batch_map_kernel<<<B_SZ, 256>>>(out);
    d2_block_kernel<<<M_BANK / 8, 256>>>(MB);
    topkA_kernel<<<dim3(SEGS, B_SZ), 256>>>();
    topk_final_kernel<<<B_SZ, 512>>>(E, MB, out);
}

// round 9
// speedup vs baseline: 12.3842x; 1.0316x over previous
#include <cuda_runtime.h>
#include <cuda_fp16.h>
#include <float.h>
#include <stdint.h>

// ---------------- problem constants ----------------
constexpr int N_ROWS  = 6272;
constexpr int M_BANK  = 32768;
constexpr int DIM     = 384;
constexpr int B_SZ    = 8;
constexpr int PATCHES = N_ROWS / B_SZ;
constexpr int KNN     = 9;

// ---------------- GEMM tiling ----------------
constexpr int BM = 128;
constexpr int BN = 256;
constexpr int BK = 128;                // K chunk (halves); stored as 2x 128B-row halves
constexpr int NCHUNK_K = DIM / BK;     // 3
constexpr int JT_TOTAL = M_BANK / BN;  // 128
constexpr int GRID_Y   = 3;            // 147 CTAs = 1 wave
constexpr int ROW_TILES = N_ROWS / BM; // 49
constexpr int NTHR = 256;              // 8 warps, ~240 regs, no spill

// SMEM: A-full resident (6 x 16KB sub-chunks) + 2 B stages x 64KB + ynorm/reduce
constexpr int A_CHUNK_BYTES = BM * 128;                   // 16384 (64-half K slice)
constexpr int OFF_B         = 6 * A_CHUNK_BYTES;          // 98304
constexpr int B_STAGE_BYTES = BN * 256;                   // 65536 (two 32KB halves)
constexpr int YN_OFF        = OFF_B + 2 * B_STAGE_BYTES;  // 229376
constexpr int SMEM_BYTES    = YN_OFF + 2048;              // 231424 (proven fit)

// top-k staging
constexpr int SEGS = 32;
constexpr int SEG_LEN = M_BANK / SEGS;  // 1024

// ---------------- device scratch ----------------
__device__ __align__(256) __half g_Eh[N_ROWS * DIM];
__device__ __align__(256) __half g_Bh[M_BANK * DIM];
__device__ float              g_xnorm[N_ROWS];
__device__ float              g_ynorm[M_BANK];
__device__ unsigned long long g_packed[N_ROWS];
__device__ float              g_d2[B_SZ * M_BANK];
__device__ unsigned long long g_part[B_SZ * SEGS * KNN];
__device__ int                g_maxrow[B_SZ];
__device__ float              g_score[B_SZ];
__device__ int                g_nnidx[B_SZ];

// ---------------- helpers ----------------
__device__ __forceinline__ uint32_t smem_u32(const void* p) {
    uint32_t a;
    asm("{ .reg .u64 t; cvta.to.shared.u64 t, %1; cvt.u32.u64 %0, t; }"
        : "=r"(a) : "l"(p));
    return a;
}
__device__ __forceinline__ void cp16(uint32_t dst, const void* src) {
    asm volatile("cp.async.cg.shared.global [%0], [%1], 16;"
                 :: "r"(dst), "l"(src) : "memory");
}
#define CP_COMMIT() asm volatile("cp.async.commit_group;" ::: "memory")
#define CP_WAIT0()  asm volatile("cp.async.wait_group 0;" ::: "memory")

__device__ __forceinline__ uint32_t swz(uint32_t o) { return o ^ ((o >> 3) & 0x70); }

__device__ __forceinline__ void ldmA(uint32_t base, int r_base, int kb,
                                     int lane, uint32_t* f) {
    int q = lane >> 3;
    int r = r_base + (q & 1) * 8 + (lane & 7);
    int kk = kb + (q >> 1) * 16;
    uint32_t a = base + swz((uint32_t)(r * 128 + kk));
    asm volatile("ldmatrix.sync.aligned.m8n8.x4.shared.b16 {%0,%1,%2,%3}, [%4];"
                 : "=r"(f[0]), "=r"(f[1]), "=r"(f[2]), "=r"(f[3]) : "r"(a));
}
__device__ __forceinline__ void ldmB4(uint32_t base, int n_base, int kb,
                                      int lane, uint32_t* f) {
    int q = lane >> 3;
    int n = n_base + (q >> 1) * 8 + (lane & 7);
    int kk = kb + (q & 1) * 16;
    uint32_t a = base + swz((uint32_t)(n * 128 + kk));
    asm volatile("ldmatrix.sync.aligned.m8n8.x4.shared.b16 {%0,%1,%2,%3}, [%4];"
                 : "=r"(f[0]), "=r"(f[1]), "=r"(f[2]), "=r"(f[3]) : "r"(a));
}
__device__ __forceinline__ void mma_f16(float* c, const uint32_t* a,
                                        const uint32_t* b) {
    asm volatile(
        "mma.sync.aligned.m16n8k16.row.col.f32.f16.f16.f32 "
        "{%0,%1,%2,%3},{%4,%5,%6,%7},{%8,%9},{%0,%1,%2,%3};"
        : "+f"(c[0]), "+f"(c[1]), "+f"(c[2]), "+f"(c[3])
        : "r"(a[0]), "r"(a[1]), "r"(a[2]), "r"(a[3]), "r"(b[0]), "r"(b[1]));
}
__device__ __forceinline__ float warp_sum(float s) {
#pragma unroll
    for (int o = 16; o; o >>= 1) s += __shfl_xor_sync(0xFFFFFFFFu, s, o);
    return s;
}
__device__ __forceinline__ unsigned long long umin64(unsigned long long a,
                                                     unsigned long long b) {
    return a < b ? a : b;
}
__device__ __forceinline__ void fold_min(unsigned long long& best, float xn,
                                         float yn, float dot, int col) {
    float d = fmaxf(fmaf(-2.f, dot, xn + yn), 0.f);
    unsigned long long p =
        ((unsigned long long)__float_as_uint(d) << 32) | (unsigned)col;
    best = umin64(best, p);
}

// ---------------- fused prep: fp16 convert + norms + packed init ----------------
__global__ void prep_all_kernel(const float* __restrict__ E,
                                const float* __restrict__ MB) {
    int warp = (blockIdx.x * blockDim.x + threadIdx.x) >> 5;
    int lane = threadIdx.x & 31;
    if (warp >= N_ROWS + M_BANK) return;
    bool isE = warp < N_ROWS;
    int row = isE ? warp : warp - N_ROWS;
    const float* src = isE ? E : MB;
    __half* dsth = isE ? g_Eh : g_Bh;
    const float4* p =
        reinterpret_cast<const float4*>(src + (size_t)row * DIM + lane * 12);
    __half2* dst =
        reinterpret_cast<__half2*>(dsth + (size_t)row * DIM + lane * 12);
    float s = 0.f;
#pragma unroll
    for (int v = 0; v < 3; v++) {
        float4 f = p[v];
        s += f.x * f.x + f.y * f.y + f.z * f.z + f.w * f.w;
        dst[v * 2]     = __floats2half2_rn(f.x, f.y);
        dst[v * 2 + 1] = __floats2half2_rn(f.z, f.w);
    }
    s = warp_sum(s);
    if (!lane) {
        if (isE) { g_xnorm[row] = s; g_packed[row] = 0xFFFFFFFFFFFFFFFFull; }
        else     g_ynorm[row] = s;
    }
}

// ---------------- B chunk (+ per-tile ynorm) loader: 64KB, two K-halves ----------------
__device__ __forceinline__ void load_B(uint32_t sb, int c, int jt0, int t) {
    const int tl  = c / NCHUNK_K;
    const int j0  = (jt0 + tl) * BN;
    const int kof = (c % NCHUNK_K) * BK;
    uint32_t sbase = sb + OFF_B + (c & 1) * B_STAGE_BYTES;
#pragma unroll
    for (int i = t; i < BN * 16; i += NTHR) {     // 16 cp16/thread
        int r = i >> 4, g = i & 15, h = g >> 3, gg = g & 7;
        uint32_t d = h * 32768 + swz((uint32_t)(r * 128 + gg * 16));
        cp16(sbase + d, g_Bh + (size_t)(j0 + r) * DIM + kof + h * 64 + gg * 8);
    }
    if ((c % NCHUNK_K) == 0 && t < 64)
        cp16(sb + YN_OFF + (tl & 1) * 1024 + t * 16, g_ynorm + j0 + t * 4);
}

// ---------------- main GEMM + fused min/argmin ----------------
__global__ __launch_bounds__(NTHR, 1) void gemm_mma_kernel() {
    extern __shared__ __align__(1024) char smem[];
    uint32_t sb = smem_u32(smem);
    const float* ynbuf = (const float*)(smem + YN_OFF);
    unsigned long long* red = (unsigned long long*)(smem + YN_OFF);

    const int t = threadIdx.x;
    const int w = t >> 5, lane = t & 31;
    const int gid = lane >> 2, tig = lane & 3;
    const int wm = w & 1, wn = w >> 1;     // warp tile: rows wm*64, cols wn*64
    const int row0 = blockIdx.x * BM;
    const int jt0 = blockIdx.y * 43;
    const int jt1 = (jt0 + 43 < JT_TOTAL) ? jt0 + 43 : JT_TOTAL;
    const int TOT = (jt1 - jt0) * NCHUNK_K;

    float xnA[4], xnB[4];
#pragma unroll
    for (int i = 0; i < 4; i++) {
        xnA[i] = g_xnorm[row0 + wm * 64 + i * 16 + gid];
        xnB[i] = g_xnorm[row0 + wm * 64 + i * 16 + gid + 8];
    }

    unsigned long long bestA[4], bestB[4];
#pragma unroll
    for (int i = 0; i < 4; i++) bestA[i] = bestB[i] = 0xFFFFFFFFFFFFFFFFull;

    // prologue: A full-K resident (6 x 16KB sub-chunks), then B chunk 0
#pragma unroll
    for (int ak = 0; ak < 6; ak++) {
        for (int i = t; i < BM * 8; i += NTHR) {
            int r = i >> 3, g = i & 7;
            uint32_t d = swz((uint32_t)(r * 128 + g * 16));
            cp16(sb + ak * A_CHUNK_BYTES + d,
                 g_Eh + (size_t)(row0 + r) * DIM + ak * 64 + g * 8);
        }
    }
    CP_COMMIT();
    load_B(sb, 0, jt0, t);
    CP_COMMIT();

    float acc[4][8][4];
#pragma unroll
    for (int i = 0; i < 4; i++)
#pragma unroll
        for (int j = 0; j < 8; j++)
#pragma unroll
            for (int q = 0; q < 4; q++) acc[i][j][q] = 0.f;

    for (int c = 0; c < TOT; c++) {
        CP_WAIT0();            // B_c (and A at c=0, ynorm) resident
        __syncthreads();       // all warps done with chunk c-1 -> stage free
        if (c + 1 < TOT) { load_B(sb, c + 1, jt0, t); CP_COMMIT(); }

        const int ck = c % NCHUNK_K;
        const uint32_t sB = sb + OFF_B + (c & 1) * B_STAGE_BYTES;

#pragma unroll
        for (int kk = 0; kk < 8; kk++) {           // BK=128 -> 8 k16 steps
            const int kb = (kk & 3) * 32;          // bytes within 128B row
            const uint32_t sA = sb + (ck * 2 + (kk >> 2)) * A_CHUNK_BYTES;
            const uint32_t sBh = sB + (kk >> 2) * 32768;
            uint32_t Af[4][4], Bf[8][2];
#pragma unroll
            for (int jj = 0; jj < 4; jj++) {
                uint32_t f[4];
                ldmB4(sBh, wn * 64 + jj * 16, kb, lane, f);
                Bf[2 * jj][0] = f[0]; Bf[2 * jj][1] = f[1];
                Bf[2 * jj + 1][0] = f[2]; Bf[2 * jj + 1][1] = f[3];
            }
#pragma unroll
            for (int i = 0; i < 4; i++)
                ldmA(sA, wm * 64 + i * 16, kb, lane, Af[i]);
#pragma unroll
            for (int i = 0; i < 4; i++)
#pragma unroll
                for (int j = 0; j < 8; j++)
                    mma_f16(acc[i][j], Af[i], Bf[j]);
        }

        if (ck == NCHUNK_K - 1) {
            const int tl = c / NCHUNK_K;
            const int j0 = (jt0 + tl) * BN;
            const float* yn = ynbuf + (tl & 1) * 256;
#pragma unroll
            for (int i = 0; i < 4; i++)
#pragma unroll
                for (int j = 0; j < 8; j++) {
                    int cl = wn * 64 + j * 8 + tig * 2;
                    float yn0 = yn[cl], yn1 = yn[cl + 1];
                    int col = j0 + cl;
                    fold_min(bestA[i], xnA[i], yn0, acc[i][j][0], col);
                    fold_min(bestA[i], xnA[i], yn1, acc[i][j][1], col + 1);
                    fold_min(bestB[i], xnB[i], yn0, acc[i][j][2], col);
                    fold_min(bestB[i], xnB[i], yn1, acc[i][j][3], col + 1);
                    acc[i][j][0] = acc[i][j][1] = acc[i][j][2] = acc[i][j][3] = 0.f;
                }
        }
    }

    // reduce across tig lanes (same row)
#pragma unroll
    for (int i = 0; i < 4; i++) {
#pragma unroll
        for (int off = 1; off <= 2; off <<= 1) {
            bestA[i] = umin64(bestA[i], __shfl_xor_sync(0xFFFFFFFFu, bestA[i], off));
            bestB[i] = umin64(bestB[i], __shfl_xor_sync(0xFFFFFFFFu, bestB[i], off));
        }
    }

    __syncthreads();   // ynorm slots dead; reuse region as reduce buffer
    if (t < BM) red[t] = 0xFFFFFFFFFFFFFFFFull;
    __syncthreads();
    if (tig == 0) {
#pragma unroll
        for (int i = 0; i < 4; i++) {
            atomicMin(&red[wm * 64 + i * 16 + gid], bestA[i]);
            atomicMin(&red[wm * 64 + i * 16 + gid + 8], bestB[i]);
        }
    }
    __syncthreads();
    if (t < BM) atomicMin(&g_packed[row0 + t], red[t]);
}

// ---------------- tail: batch argmax + patch map write (fused) ----------------
__global__ void batch_map_kernel(float* __restrict__ out) {
    int b = blockIdx.x, t = threadIdx.x;
    __shared__ float sv[256];
    __shared__ int   si[256];
    float bv = -1.f; int bi = PATCHES;
    for (int p = t; p < PATCHES; p += 256) {
        unsigned long long pk = g_packed[b * PATCHES + p];
        float d = __uint_as_float((unsigned)(pk >> 32));
        out[b * PATCHES + p] = sqrtf(d);
        if (d > bv || (d == bv && p < bi)) { bv = d; bi = p; }
    }
    sv[t] = bv; si[t] = bi;
    __syncthreads();
    for (int s = 128; s; s >>= 1) {
        if (t < s) {
            if (sv[t + s] > sv[t] || (sv[t + s] == sv[t] && si[t + s] < si[t])) {
                sv[t] = sv[t + s]; si[t] = si[t + s];
            }
        }
        __syncthreads();
    }
    if (t == 0) {
        int row = b * PATCHES + si[0];
        unsigned long long pk = g_packed[row];
        g_maxrow[b] = row;
        g_score[b]  = sqrtf(__uint_as_float((unsigned)(pk >> 32)));
        g_nnidx[b]  = (int)(pk & 0xFFFFFFFFull);
    }
}

// ---------------- d2: fp16 bank (L2-warm), all 8 batches per pass ----------------
__global__ void d2_block_kernel() {
    __shared__ float nnf[B_SZ][DIM];   // 12 KB
    __shared__ float nyn[B_SZ];
    int t = threadIdx.x, wid = t >> 5, lane = t & 31;
    for (int i = t; i < B_SZ * DIM; i += 256) {
        int b = i / DIM, k = i % DIM;
        nnf[b][k] = __half2float(g_Bh[(size_t)g_nnidx[b] * DIM + k]);
    }
    if (t < B_SZ) nyn[t] = g_ynorm[g_nnidx[t]];
    __syncthreads();

    int m = blockIdx.x * 8 + wid;
    const __half2* pm2 =
        reinterpret_cast<const __half2*>(g_Bh + (size_t)m * DIM);
    float s[B_SZ];
#pragma unroll
    for (int b = 0; b < B_SZ; b++) s[b] = 0.f;
    int k0 = lane * 12;
#pragma unroll
    for (int u = 0; u < 6; u++) {
        float2 f = __half22float2(pm2[lane * 6 + u]);
#pragma unroll
        for (int b = 0; b < B_SZ; b++)
            s[b] += f.x * nnf[b][k0 + 2 * u] + f.y * nnf[b][k0 + 2 * u + 1];
    }
#pragma unroll
    for (int b = 0; b < B_SZ; b++) s[b] = warp_sum(s[b]);
    if (lane == 0) {
        float ym = g_ynorm[m];
#pragma unroll
        for (int b = 0; b < B_SZ; b++)
            g_d2[b * M_BANK + m] = fmaxf(nyn[b] + ym - 2.f * s[b], 0.f);
    }
}

// ---------------- top-9 stage A: per-segment selection ----------------
__global__ void topkA_kernel() {
    __shared__ unsigned long long vals[SEG_LEN];
    __shared__ unsigned long long red[256];
    int b = blockIdx.y, seg = blockIdx.x, t = threadIdx.x;
    for (int i = t; i < SEG_LEN; i += 256) {
        int m = seg * SEG_LEN + i;
        vals[i] = ((unsigned long long)__float_as_uint(g_d2[b * M_BANK + m]) << 32)
                  | (unsigned)m;
    }
    __syncthreads();
    for (int r = 0; r < KNN; r++) {
        unsigned long long mv = vals[t];
        mv = umin64(mv, vals[t + 256]);
        mv = umin64(mv, vals[t + 512]);
        mv = umin64(mv, vals[t + 768]);
        red[t] = mv;
        __syncthreads();
        for (int s = 128; s; s >>= 1) {
            if (t < s) red[t] = umin64(red[t], red[t + s]);
            __syncthreads();
        }
        if (t == 0) {
            unsigned long long sel = red[0];
            g_part[(b * SEGS + seg) * KNN + r] = sel;
            vals[(unsigned)sel - seg * SEG_LEN] = 0xFFFFFFFFFFFFFFFFull;
        }
        __syncthreads();
    }
}

// ---------------- top-9 merge + final score (fused) ----------------
__global__ void topk_final_kernel(const float* __restrict__ E,
                                  const float* __restrict__ MB,
                                  float* __restrict__ out) {
    __shared__ unsigned long long cand[512];
    __shared__ unsigned long long red[512];
    __shared__ int   sup[KNN];
    __shared__ float d3[KNN];
    int b = blockIdx.x, t = threadIdx.x;
    cand[t] = (t < SEGS * KNN) ? g_part[b * SEGS * KNN + t]
                               : 0xFFFFFFFFFFFFFFFFull;
    __syncthreads();
    for (int r = 0; r < KNN; r++) {
        red[t] = cand[t];
        __syncthreads();
        for (int s = 256; s; s >>= 1) {
            if (t < s) red[t] = umin64(red[t], red[t + s]);
            __syncthreads();
        }
        unsigned long long sel = red[0];
        if (t == 0) sup[r] = (int)(sel & 0xFFFFFFFFull);
        if (cand[t] == sel) cand[t] = 0xFFFFFFFFFFFFFFFFull;
        __syncthreads();
    }

    int wid = t >> 5, lane = t & 31;
    int row = g_maxrow[b];
    if (wid < KNN) {
        const float* xf = E + (size_t)row * DIM;
        int sp = sup[wid];
        const float* pv = MB + (size_t)sp * DIM;
        float s = 0.f;
        for (int k = lane; k < DIM; k += 32) s += xf[k] * pv[k];
        s = warp_sum(s);
        if (!lane)
            d3[wid] = sqrtf(fmaxf(g_xnorm[row] + g_ynorm[sp] - 2.f * s, 0.f));
    }
    __syncthreads();
    if (t == 0) {
        float mx = -FLT_MAX;
        for (int j = 0; j < KNN; j++) mx = fmaxf(mx, d3[j]);
        float den = 0.f, e0 = 0.f;
        for (int j = 0; j < KNN; j++) {
            float e = expf(d3[j] - mx);
            den += e;
            if (j == 0) e0 = e;
        }
        out[N_ROWS + b] = (1.f - e0 / den) * g_score[b];
    }
}

// ---------------- launch ----------------
extern "C" void kernel_launch(void* const* d_in, const int* in_sizes, int n_in,
                              void* d_out, int out_size) {
    (void)n_in; (void)in_sizes; (void)out_size;
    const float* E  = (const float*)d_in[0];
    const float* MB = (const float*)d_in[1];
    float* out = (float*)d_out;

    cudaFuncSetAttribute(gemm_mma_kernel,
                         cudaFuncAttributeMaxDynamicSharedMemorySize, SMEM_BYTES);

    int warps = N_ROWS + M_BANK;
    prep_all_kernel<<<(warps * 32 + 255) / 256, 256>>>(E, MB);

    gemm_mma_kernel<<<dim3(ROW_TILES, GRID_Y), NTHR, SMEM_BYTES>>>();

    batch_map_kernel<<<B_SZ, 256>>>(out);
    d2_block_kernel<<<M_BANK / 8, 256>>>();
    topkA_kernel<<<dim3(SEGS, B_SZ), 256>>>();
    topk_final_kernel<<<B_SZ, 512>>>(E, MB, out);
}